// round 3
// baseline (speedup 1.0000x reference)
#include <cuda_runtime.h>
#include <math.h>

#define N_NODES 20000
#define D_IN 256
#define H1 128
#define H2 16
#define KG_E 200000
#define SL_E 20000
#define NG 8
#define TOT_EDGES (SL_E + 7 * KG_E)
#define E_CNN 40000
#define CNN_THREADS 128

// -------- scratch (device globals; no allocation allowed) --------
__device__ float g_xw1[NG * N_NODES * H1];   // x @ W1 per graph
__device__ float g_agg1[NG * N_NODES * H1];  // layer1 aggregation
__device__ float g_xw2[NG * N_NODES * H2];   // h @ W2 per graph
__device__ float g_agg2[NG * N_NODES * H2];  // layer2 aggregation
__device__ float g_emb[NG * N_NODES * H2];   // final embeddings (slot0=sl, 1..7=kg0..6)
__device__ int   g_deg[NG * N_NODES];
__device__ float g_dis[NG * N_NODES];

// emb_all row k -> slot in g_emb.
// kg order: 0=ppi,1=reactome,2=corum,3=go_f,4=go_c,5=go_p,6=kegg (slot = idx+1)
// emb_all = [sl, reactome, sl, kegg, sl, go_f, sl, corum, sl, go_c, sl, go_p, sl, ppi]
__constant__ int c_slot[14] = {0, 2, 0, 7, 0, 4, 0, 3, 0, 5, 0, 6, 0, 1};

// -------- helpers: flattened edge id -> (graph, src, dst) --------
__device__ __forceinline__ void decode_edge(int eid, const int* __restrict__ sl_pos,
                                            const int* __restrict__ kg_edges,
                                            int& g, int& src, int& dst) {
    if (eid < SL_E) {
        g = 0;
        src = sl_pos[eid];
        dst = sl_pos[SL_E + eid];
    } else {
        int r = eid - SL_E;
        int gg = r / KG_E;
        int i = r - gg * KG_E;
        g = gg + 1;
        const int* base = kg_edges + gg * 2 * KG_E;
        src = base[i];
        dst = base[KG_E + i];
    }
}

// -------- degree (dst-degree, self loop added in dis) --------
__global__ void degree_kernel(const int* __restrict__ sl_pos, const int* __restrict__ kg_edges) {
    int e = blockIdx.x * blockDim.x + threadIdx.x;
    if (e >= TOT_EDGES) return;
    int g, dst;
    if (e < SL_E) {
        g = 0;
        dst = sl_pos[SL_E + e];
    } else {
        int r = e - SL_E;
        int gg = r / KG_E;
        int i = r - gg * KG_E;
        g = gg + 1;
        dst = kg_edges[gg * 2 * KG_E + KG_E + i];
    }
    atomicAdd(&g_deg[g * N_NODES + dst], 1);
}

__global__ void dis_kernel() {
    int i = blockIdx.x * blockDim.x + threadIdx.x;
    if (i < NG * N_NODES) g_dis[i] = rsqrtf((float)(g_deg[i] + 1));
}

// -------- GEMM1: xw1[g] = x @ W1_g   (N x 256) @ (256 x 128) --------
// block: 256 threads, 64 rows x 128 cols tile; thread -> 8 rows x 4 cols
__global__ void gemm1_kernel(const float* __restrict__ x,
                             const float* __restrict__ Wsl1,
                             const float* __restrict__ Wkg1) {
    __shared__ float As[64][16];
    __shared__ float Bs[16][128];
    int g = blockIdx.y;
    const float* B = (g == 0) ? Wsl1 : (Wkg1 + (g - 1) * D_IN * H1);
    int row0 = blockIdx.x * 64;
    int t = threadIdx.x;
    int tx = t & 31, ty = t >> 5;
    float acc[8][4];
#pragma unroll
    for (int r = 0; r < 8; r++)
#pragma unroll
        for (int q = 0; q < 4; q++) acc[r][q] = 0.f;

    int ai = t >> 2, aq = (t & 3) << 2;
    for (int kb = 0; kb < D_IN; kb += 16) {
        int arow = row0 + ai;
        float4 av = make_float4(0.f, 0.f, 0.f, 0.f);
        if (arow < N_NODES) av = *(const float4*)&x[arow * D_IN + kb + aq];
        *(float4*)&As[ai][aq] = av;
#pragma unroll
        for (int l = 0; l < 2; l++) {
            int lin = t + l * 256;
            int bk = lin >> 5, bq = (lin & 31) << 2;
            *(float4*)&Bs[bk][bq] = *(const float4*)&B[(kb + bk) * H1 + bq];
        }
        __syncthreads();
#pragma unroll
        for (int k = 0; k < 16; k++) {
            float4 b = *(float4*)&Bs[k][tx << 2];
#pragma unroll
            for (int r = 0; r < 8; r++) {
                float a = As[ty + (r << 3)][k];
                acc[r][0] += a * b.x;
                acc[r][1] += a * b.y;
                acc[r][2] += a * b.z;
                acc[r][3] += a * b.w;
            }
        }
        __syncthreads();
    }
#pragma unroll
    for (int r = 0; r < 8; r++) {
        int row = row0 + ty + (r << 3);
        if (row < N_NODES)
            *(float4*)&g_xw1[(g * N_NODES + row) * H1 + (tx << 2)] =
                make_float4(acc[r][0], acc[r][1], acc[r][2], acc[r][3]);
    }
}

// -------- scatter layer1: agg1[dst] += dis[src]*dis[dst] * xw1[src] --------
// 32 lanes per edge, float4 atomics (8 edges per 256-thread block)
__global__ void scatter1_kernel(const int* __restrict__ sl_pos, const int* __restrict__ kg_edges) {
    int eid = blockIdx.x * 8 + (threadIdx.x >> 5);
    if (eid >= TOT_EDGES) return;
    int lane = threadIdx.x & 31;
    int g, src, dst;
    decode_edge(eid, sl_pos, kg_edges, g, src, dst);
    float norm = g_dis[g * N_NODES + src] * g_dis[g * N_NODES + dst];
    const float4 v = *(const float4*)&g_xw1[(g * N_NODES + src) * H1 + (lane << 2)];
    float4 a = make_float4(v.x * norm, v.y * norm, v.z * norm, v.w * norm);
    atomicAdd((float4*)&g_agg1[(g * N_NODES + dst) * H1 + (lane << 2)], a);
}

// -------- h = relu(agg1 + dis^2*xw1 + b1); xw2 = h @ W2  (128 -> 16) --------
// block: 256 threads, 16 rows per block
__global__ void gemm2_kernel(const float* __restrict__ Wsl2, const float* __restrict__ Wkg2,
                             const float* __restrict__ bsl1, const float* __restrict__ bkg1) {
    __shared__ float hs[16 * 128];
    __shared__ float w2s[128 * 16];
    int g = blockIdx.y;
    int n0 = blockIdx.x * 16;
    const float* W2 = (g == 0) ? Wsl2 : (Wkg2 + (g - 1) * H1 * H2);
    const float* b1 = (g == 0) ? bsl1 : (bkg1 + (g - 1) * H1);
    int t = threadIdx.x;
    for (int idx = t; idx < H1 * H2; idx += 256) w2s[idx] = W2[idx];
    for (int idx = t; idx < 16 * H1; idx += 256) {
        int r = idx >> 7, k = idx & 127;
        int n = n0 + r;
        float h = 0.f;
        if (n < N_NODES) {
            float dis = g_dis[g * N_NODES + n];
            int base = (g * N_NODES + n) * H1 + k;
            h = g_agg1[base] + dis * dis * g_xw1[base] + b1[k];
            h = fmaxf(h, 0.f);
        }
        hs[idx] = h;
    }
    __syncthreads();
    int r = t >> 4, j = t & 15;
    int n = n0 + r;
    if (n < N_NODES) {
        float acc = 0.f;
#pragma unroll 8
        for (int k = 0; k < H1; k++) acc += hs[r * 128 + k] * w2s[k * 16 + j];
        g_xw2[(g * N_NODES + n) * H2 + j] = acc;
    }
}

// -------- scatter layer2: agg2[dst] += norm * xw2[src]  (16 feats, 4 lanes/edge) --------
__global__ void scatter2_kernel(const int* __restrict__ sl_pos, const int* __restrict__ kg_edges) {
    int eid = blockIdx.x * 64 + (threadIdx.x >> 2);
    if (eid >= TOT_EDGES) return;
    int lane = threadIdx.x & 3;
    int g, src, dst;
    decode_edge(eid, sl_pos, kg_edges, g, src, dst);
    float norm = g_dis[g * N_NODES + src] * g_dis[g * N_NODES + dst];
    const float4 v = *(const float4*)&g_xw2[(g * N_NODES + src) * H2 + (lane << 2)];
    float4 a = make_float4(v.x * norm, v.y * norm, v.z * norm, v.w * norm);
    atomicAdd((float4*)&g_agg2[(g * N_NODES + dst) * H2 + (lane << 2)], a);
}

// -------- emb = agg2 + dis^2*xw2 + b2 --------
__global__ void emb_kernel(const float* __restrict__ bsl2, const float* __restrict__ bkg2) {
    int idx = blockIdx.x * blockDim.x + threadIdx.x;
    if (idx >= NG * N_NODES * H2) return;
    int g = idx / (N_NODES * H2);
    int rem = idx - g * (N_NODES * H2);
    int n = rem >> 4;
    int d = rem & 15;
    float dis = g_dis[g * N_NODES + n];
    float b = (g == 0) ? bsl2[d] : bkg2[(g - 1) * 16 + d];
    g_emb[idx] = g_agg2[idx] + dis * dis * g_xw2[idx] + b;
}

// -------- per-edge CNN (persistent blocks) --------
struct CnnSmem {
    float w2s[32 * 9 * 64];  // conv2 weights, [c][k][o] (o-major -> conflict-free)
    float l1w[32 * 64];
    float w1s[32 * 8];       // conv1 weights [o][c*4+di*2+dj]
    float c1b[32];
    float c2b[64];
    float l1b[32];
    float l2w[32];
    float l2b[1];
    float img[2 * 14 * 16];
    float pooled[32 * 6 * 8];  // [c][y][x], x padded to 8
    float red[128];
    float feats[64];
    float h2s[32];
};

__global__ void cnn_kernel(const int* __restrict__ sl_pos, const int* __restrict__ sl_neg,
                           const float* __restrict__ conv1_w, const float* __restrict__ conv1_b,
                           const float* __restrict__ conv2_w, const float* __restrict__ conv2_b,
                           const float* __restrict__ lin1_w, const float* __restrict__ lin1_b,
                           const float* __restrict__ lin2_w, const float* __restrict__ lin2_b,
                           float* __restrict__ out) {
    extern __shared__ char smem_raw[];
    CnnSmem* s = reinterpret_cast<CnnSmem*>(smem_raw);
    int t = threadIdx.x;

    // ---- load all weights once per block ----
    for (int i = t; i < 64 * 32 * 9; i += CNN_THREADS) {
        int o = i / 288;
        int rem = i - o * 288;  // c*9 + k
        s->w2s[rem * 64 + o] = conv2_w[i];
    }
    for (int i = t; i < 32 * 64; i += CNN_THREADS) s->l1w[i] = lin1_w[i];
    for (int i = t; i < 256; i += CNN_THREADS) s->w1s[i] = conv1_w[i];
    if (t < 32) s->c1b[t] = conv1_b[t];
    if (t < 64) s->c2b[t] = conv2_b[t];
    if (t < 32) s->l1b[t] = lin1_b[t];
    if (t < 32) s->l2w[t] = lin2_w[t];
    if (t == 0) s->l2b[0] = lin2_b[0];
    __syncthreads();

    for (int e = blockIdx.x; e < E_CNN; e += gridDim.x) {
        int n0, n1;
        if (e < SL_E) {
            n0 = sl_pos[e];
            n1 = sl_pos[SL_E + e];
        } else {
            n0 = sl_neg[e - SL_E];
            n1 = sl_neg[e];
        }

        // ---- phase 1: gather image [2][14][16] ----
        for (int idx = t; idx < 448; idx += CNN_THREADS) {
            int c = idx / 224;
            int rem = idx - c * 224;
            int k = rem >> 4;
            int d = rem & 15;
            int node = c ? n1 : n0;
            s->img[idx] = g_emb[(c_slot[k] * N_NODES + node) * H2 + d];
        }
        __syncthreads();

        // ---- phase 2: conv1 + maxpool fused -> pooled [32][6][7] ----
        for (int idx = t; idx < 32 * 6 * 7; idx += CNN_THREADS) {
            int o = idx / 42;
            int rem = idx - o * 42;
            int y = rem / 7;
            int xx = rem - y * 7;
            const float* wv = &s->w1s[o * 8];
            float w0 = wv[0], w1 = wv[1], w2 = wv[2], w3 = wv[3];
            float w4 = wv[4], w5 = wv[5], w6 = wv[6], w7 = wv[7];
            float bb = s->c1b[o];
            float m = -1e30f;
#pragma unroll
            for (int ii = 0; ii < 2; ii++) {
#pragma unroll
                for (int jj = 0; jj < 2; jj++) {
                    int i = 2 * y + ii, j = 2 * xx + jj;
                    const float* i0p = &s->img[i * 16 + j];
                    const float* i1p = &s->img[224 + i * 16 + j];
                    float v = bb + w0 * i0p[0] + w1 * i0p[1] + w2 * i0p[16] + w3 * i0p[17] +
                              w4 * i1p[0] + w5 * i1p[1] + w6 * i1p[16] + w7 * i1p[17];
                    m = fmaxf(m, v);
                }
            }
            s->pooled[o * 48 + y * 8 + xx] = m;
        }
        __syncthreads();

        // ---- phase 3: conv2 [64][4][5] + maxpool2 + global max ----
        {
            int o = t >> 1, half = t & 1, i0 = half * 2;
            float acc[2][5];
            float bb = s->c2b[o];
#pragma unroll
            for (int ii = 0; ii < 2; ii++)
#pragma unroll
                for (int j = 0; j < 5; j++) acc[ii][j] = bb;
            for (int c = 0; c < 32; c++) {
                float r[4][7];
                const float* p = &s->pooled[c * 48 + i0 * 8];
#pragma unroll
                for (int a = 0; a < 4; a++)
#pragma unroll
                    for (int bx = 0; bx < 7; bx++) r[a][bx] = p[a * 8 + bx];
                const float* wp = &s->w2s[c * 9 * 64 + o];
#pragma unroll
                for (int di = 0; di < 3; di++) {
#pragma unroll
                    for (int dj = 0; dj < 3; dj++) {
                        float w = wp[(di * 3 + dj) * 64];
#pragma unroll
                        for (int ii = 0; ii < 2; ii++)
#pragma unroll
                            for (int j = 0; j < 5; j++) acc[ii][j] += w * r[ii + di][j + dj];
                    }
                }
            }
            // maxpool2 (drops j=4) then adaptive max -> max over i(local) 0..1, j 0..3
            float m = -1e30f;
#pragma unroll
            for (int ii = 0; ii < 2; ii++)
#pragma unroll
                for (int j = 0; j < 4; j++) m = fmaxf(m, acc[ii][j]);
            s->red[t] = m;
        }
        __syncthreads();
        if (t < 64) s->feats[t] = fmaxf(s->red[2 * t], s->red[2 * t + 1]);
        __syncthreads();
        if (t < 32) {
            float acc = s->l1b[t];
#pragma unroll 16
            for (int d = 0; d < 64; d++) acc += s->feats[d] * s->l1w[t * 64 + d];
            s->h2s[t] = fmaxf(acc, 0.f);
        }
        __syncthreads();
        if (t == 0) {
            float y = s->l2b[0];
#pragma unroll
            for (int d = 0; d < 32; d++) y += s->h2s[d] * s->l2w[d];
            out[e] = 1.f / (1.f + expf(-y));
        }
        __syncthreads();
    }
}

// -------- launch --------
extern "C" void kernel_launch(void* const* d_in, const int* in_sizes, int n_in,
                              void* d_out, int out_size) {
    const float* x       = (const float*)d_in[0];
    const int*   sl_pos  = (const int*)d_in[1];
    const int*   sl_neg  = (const int*)d_in[2];
    const int*   kg_edges= (const int*)d_in[3];
    const float* Wsl1    = (const float*)d_in[4];
    const float* bsl1    = (const float*)d_in[5];
    const float* Wsl2    = (const float*)d_in[6];
    const float* bsl2    = (const float*)d_in[7];
    const float* Wkg1    = (const float*)d_in[8];
    const float* bkg1    = (const float*)d_in[9];
    const float* Wkg2    = (const float*)d_in[10];
    const float* bkg2    = (const float*)d_in[11];
    const float* conv1_w = (const float*)d_in[12];
    const float* conv1_b = (const float*)d_in[13];
    const float* conv2_w = (const float*)d_in[14];
    const float* conv2_b = (const float*)d_in[15];
    const float* lin1_w  = (const float*)d_in[16];
    const float* lin1_b  = (const float*)d_in[17];
    const float* lin2_w  = (const float*)d_in[18];
    const float* lin2_b  = (const float*)d_in[19];
    float* out = (float*)d_out;

    void *p_agg1, *p_agg2, *p_deg;
    cudaGetSymbolAddress(&p_agg1, g_agg1);
    cudaGetSymbolAddress(&p_agg2, g_agg2);
    cudaGetSymbolAddress(&p_deg, g_deg);
    cudaMemsetAsync(p_agg1, 0, sizeof(float) * NG * N_NODES * H1);
    cudaMemsetAsync(p_agg2, 0, sizeof(float) * NG * N_NODES * H2);
    cudaMemsetAsync(p_deg, 0, sizeof(int) * NG * N_NODES);

    degree_kernel<<<(TOT_EDGES + 255) / 256, 256>>>(sl_pos, kg_edges);
    dis_kernel<<<(NG * N_NODES + 255) / 256, 256>>>();
    gemm1_kernel<<<dim3((N_NODES + 63) / 64, NG), 256>>>(x, Wsl1, Wkg1);
    scatter1_kernel<<<(TOT_EDGES + 7) / 8, 256>>>(sl_pos, kg_edges);
    gemm2_kernel<<<dim3((N_NODES + 15) / 16, NG), 256>>>(Wsl2, Wkg2, bsl1, bkg1);
    scatter2_kernel<<<(TOT_EDGES + 63) / 64, 256>>>(sl_pos, kg_edges);
    emb_kernel<<<(NG * N_NODES * H2 + 255) / 256, 256>>>(bsl2, bkg2);

    cudaFuncSetAttribute(cnn_kernel, cudaFuncAttributeMaxDynamicSharedMemorySize,
                         (int)sizeof(CnnSmem));
    cnn_kernel<<<296, CNN_THREADS, sizeof(CnnSmem)>>>(
        sl_pos, sl_neg, conv1_w, conv1_b, conv2_w, conv2_b,
        lin1_w, lin1_b, lin2_w, lin2_b, out);
}

// round 6
// speedup vs baseline: 1.1506x; 1.1506x over previous
#include <cuda_runtime.h>
#include <math.h>

#define N_NODES 20000
#define D_IN 256
#define H1 128
#define H2 16
#define KG_E 200000
#define SL_E 20000
#define NG 8
#define TOT_EDGES (SL_E + 7 * KG_E)
#define E_CNN 40000
#define CNN_THREADS 256

// -------- packed f32x2 helpers (sm_100a) --------
typedef unsigned long long u64t;
__device__ __forceinline__ u64t pk2(float lo, float hi) {
    u64t r;
    asm("mov.b64 %0, {%1, %2};" : "=l"(r) : "r"(__float_as_uint(lo)), "r"(__float_as_uint(hi)));
    return r;
}
__device__ __forceinline__ u64t fma2(u64t a, u64t b, u64t c) {
    u64t d;
    asm("fma.rn.f32x2 %0, %1, %2, %3;" : "=l"(d) : "l"(a), "l"(b), "l"(c));
    return d;
}
__device__ __forceinline__ float2 upk2(u64t v) {
    unsigned int lo, hi;
    asm("mov.b64 {%0, %1}, %2;" : "=r"(lo), "=r"(hi) : "l"(v));
    return make_float2(__uint_as_float(lo), __uint_as_float(hi));
}

// -------- scratch (device globals; no allocation allowed) --------
__device__ float g_xw1[NG * N_NODES * H1];
__device__ float g_agg1[NG * N_NODES * H1];
__device__ float g_xw2[NG * N_NODES * H2];
__device__ float g_agg2[NG * N_NODES * H2];
__device__ float g_emb[NG * N_NODES * H2];
__device__ int   g_deg[NG * N_NODES];
__device__ float g_dis[NG * N_NODES];

// emb_all row k -> slot in g_emb (slot0=sl, 1..7 = ppi,reactome,corum,go_f,go_c,go_p,kegg)
__constant__ int c_slot[14] = {0, 2, 0, 7, 0, 4, 0, 3, 0, 5, 0, 6, 0, 1};

__device__ __forceinline__ void decode_edge(int eid, const int* __restrict__ sl_pos,
                                            const int* __restrict__ kg_edges,
                                            int& g, int& src, int& dst) {
    if (eid < SL_E) {
        g = 0;
        src = sl_pos[eid];
        dst = sl_pos[SL_E + eid];
    } else {
        int r = eid - SL_E;
        int gg = r / KG_E;
        int i = r - gg * KG_E;
        g = gg + 1;
        const int* base = kg_edges + gg * 2 * KG_E;
        src = base[i];
        dst = base[KG_E + i];
    }
}

// -------- degree --------
__global__ void degree_kernel(const int* __restrict__ sl_pos, const int* __restrict__ kg_edges) {
    int e = blockIdx.x * blockDim.x + threadIdx.x;
    if (e >= TOT_EDGES) return;
    int g, dst;
    if (e < SL_E) {
        g = 0;
        dst = sl_pos[SL_E + e];
    } else {
        int r = e - SL_E;
        int gg = r / KG_E;
        int i = r - gg * KG_E;
        g = gg + 1;
        dst = kg_edges[gg * 2 * KG_E + KG_E + i];
    }
    atomicAdd(&g_deg[g * N_NODES + dst], 1);
}

__global__ void dis_kernel() {
    int i = blockIdx.x * blockDim.x + threadIdx.x;
    if (i < NG * N_NODES) g_dis[i] = rsqrtf((float)(g_deg[i] + 1));
}

// -------- GEMM1: xw1[g] = x @ W1_g  (packed f32x2) --------
__global__ void gemm1_kernel(const float* __restrict__ x,
                             const float* __restrict__ Wsl1,
                             const float* __restrict__ Wkg1) {
    __shared__ float As[64][16];
    __shared__ float Bs[16][128];
    int g = blockIdx.y;
    const float* B = (g == 0) ? Wsl1 : (Wkg1 + (g - 1) * D_IN * H1);
    int row0 = blockIdx.x * 64;
    int t = threadIdx.x;
    int tx = t & 31, ty = t >> 5;
    u64t acc2[8][2];
#pragma unroll
    for (int r = 0; r < 8; r++) {
        acc2[r][0] = 0ull;
        acc2[r][1] = 0ull;
    }

    int ai = t >> 2, aq = (t & 3) << 2;
    for (int kb = 0; kb < D_IN; kb += 16) {
        int arow = row0 + ai;
        float4 av = make_float4(0.f, 0.f, 0.f, 0.f);
        if (arow < N_NODES) av = *(const float4*)&x[arow * D_IN + kb + aq];
        *(float4*)&As[ai][aq] = av;
#pragma unroll
        for (int l = 0; l < 2; l++) {
            int lin = t + l * 256;
            int bk = lin >> 5, bq = (lin & 31) << 2;
            *(float4*)&Bs[bk][bq] = *(const float4*)&B[(kb + bk) * H1 + bq];
        }
        __syncthreads();
#pragma unroll
        for (int k = 0; k < 16; k++) {
            float4 b = *(float4*)&Bs[k][tx << 2];
            u64t b01 = pk2(b.x, b.y);
            u64t b23 = pk2(b.z, b.w);
#pragma unroll
            for (int r = 0; r < 8; r++) {
                float a = As[ty + (r << 3)][k];
                u64t aa = pk2(a, a);
                acc2[r][0] = fma2(aa, b01, acc2[r][0]);
                acc2[r][1] = fma2(aa, b23, acc2[r][1]);
            }
        }
        __syncthreads();
    }
#pragma unroll
    for (int r = 0; r < 8; r++) {
        int row = row0 + ty + (r << 3);
        if (row < N_NODES) {
            float2 lo = upk2(acc2[r][0]);
            float2 hi = upk2(acc2[r][1]);
            *(float4*)&g_xw1[(g * N_NODES + row) * H1 + (tx << 2)] =
                make_float4(lo.x, lo.y, hi.x, hi.y);
        }
    }
}

// -------- scatter layer1 --------
__global__ void scatter1_kernel(const int* __restrict__ sl_pos, const int* __restrict__ kg_edges) {
    int eid = blockIdx.x * 8 + (threadIdx.x >> 5);
    if (eid >= TOT_EDGES) return;
    int lane = threadIdx.x & 31;
    int g, src, dst;
    decode_edge(eid, sl_pos, kg_edges, g, src, dst);
    float norm = g_dis[g * N_NODES + src] * g_dis[g * N_NODES + dst];
    const float4 v = *(const float4*)&g_xw1[(g * N_NODES + src) * H1 + (lane << 2)];
    float4 a = make_float4(v.x * norm, v.y * norm, v.z * norm, v.w * norm);
    atomicAdd((float4*)&g_agg1[(g * N_NODES + dst) * H1 + (lane << 2)], a);
}

// -------- h = relu(agg1 + dis^2*xw1 + b1); xw2 = h @ W2 --------
__global__ void gemm2_kernel(const float* __restrict__ Wsl2, const float* __restrict__ Wkg2,
                             const float* __restrict__ bsl1, const float* __restrict__ bkg1) {
    __shared__ float hs[16 * 128];
    __shared__ float w2s[128 * 16];
    int g = blockIdx.y;
    int n0 = blockIdx.x * 16;
    const float* W2 = (g == 0) ? Wsl2 : (Wkg2 + (g - 1) * H1 * H2);
    const float* b1 = (g == 0) ? bsl1 : (bkg1 + (g - 1) * H1);
    int t = threadIdx.x;
    for (int idx = t; idx < H1 * H2; idx += 256) w2s[idx] = W2[idx];
    for (int idx = t; idx < 16 * H1; idx += 256) {
        int r = idx >> 7, k = idx & 127;
        int n = n0 + r;
        float h = 0.f;
        if (n < N_NODES) {
            float dis = g_dis[g * N_NODES + n];
            int base = (g * N_NODES + n) * H1 + k;
            h = g_agg1[base] + dis * dis * g_xw1[base] + b1[k];
            h = fmaxf(h, 0.f);
        }
        hs[idx] = h;
    }
    __syncthreads();
    int r = t >> 4, j = t & 15;
    int n = n0 + r;
    if (n < N_NODES) {
        float acc = 0.f;
#pragma unroll 8
        for (int k = 0; k < H1; k++) acc += hs[r * 128 + k] * w2s[k * 16 + j];
        g_xw2[(g * N_NODES + n) * H2 + j] = acc;
    }
}

// -------- scatter layer2 --------
__global__ void scatter2_kernel(const int* __restrict__ sl_pos, const int* __restrict__ kg_edges) {
    int eid = blockIdx.x * 64 + (threadIdx.x >> 2);
    if (eid >= TOT_EDGES) return;
    int lane = threadIdx.x & 3;
    int g, src, dst;
    decode_edge(eid, sl_pos, kg_edges, g, src, dst);
    float norm = g_dis[g * N_NODES + src] * g_dis[g * N_NODES + dst];
    const float4 v = *(const float4*)&g_xw2[(g * N_NODES + src) * H2 + (lane << 2)];
    float4 a = make_float4(v.x * norm, v.y * norm, v.z * norm, v.w * norm);
    atomicAdd((float4*)&g_agg2[(g * N_NODES + dst) * H2 + (lane << 2)], a);
}

// -------- emb = agg2 + dis^2*xw2 + b2 --------
__global__ void emb_kernel(const float* __restrict__ bsl2, const float* __restrict__ bkg2) {
    int idx = blockIdx.x * blockDim.x + threadIdx.x;
    if (idx >= NG * N_NODES * H2) return;
    int g = idx / (N_NODES * H2);
    int rem = idx - g * (N_NODES * H2);
    int n = rem >> 4;
    int d = rem & 15;
    float dis = g_dis[g * N_NODES + n];
    float b = (g == 0) ? bsl2[d] : bkg2[(g - 1) * 16 + d];
    g_emb[idx] = g_agg2[idx] + dis * dis * g_xw2[idx] + b;
}

// -------- per-edge CNN: 2 edges per 256-thread block, f32x2 conv2 --------
// NOTE: field order/padding chosen so img and pooled start 16B-aligned
// (l2b padded to 4 floats — the R5 'misaligned address' fix).
struct CnnSmem {
    float w2s[32 * 9 * 64];   // 18432 floats, offset 0
    float l1w[32 * 64];       // 2048
    float w1s[32 * 8];        // 256
    float c1b[32];
    float c2b[64];
    float l1b[32];
    float l2w[32];
    float l2b[4];             // padded: keeps img/pooled 16B-aligned
    float img[2][2 * 14 * 16];    // offset 20900 floats = 83600 B (16B-aligned)
    float pooled[2][32 * 6 * 8];  // offset 21796 floats = 87184 B (16B-aligned)
    float red[2][128];
    float feats[2][64];
    float h2s[2][32];
};

__global__ __launch_bounds__(CNN_THREADS, 2)
void cnn_kernel(const int* __restrict__ sl_pos, const int* __restrict__ sl_neg,
                const float* __restrict__ conv1_w, const float* __restrict__ conv1_b,
                const float* __restrict__ conv2_w, const float* __restrict__ conv2_b,
                const float* __restrict__ lin1_w, const float* __restrict__ lin1_b,
                const float* __restrict__ lin2_w, const float* __restrict__ lin2_b,
                float* __restrict__ out) {
    extern __shared__ __align__(16) char smem_raw[];
    CnnSmem* s = reinterpret_cast<CnnSmem*>(smem_raw);
    int t = threadIdx.x;
    int sub = t >> 7;       // which edge slot (0/1)
    int wt = t & 127;       // thread id within sub-block

    // ---- load all weights once per block ----
    for (int i = t; i < 64 * 32 * 9; i += CNN_THREADS) {
        int o = i / 288;
        int rem = i - o * 288;  // c*9 + k
        s->w2s[rem * 64 + o] = conv2_w[i];
    }
    for (int i = t; i < 32 * 64; i += CNN_THREADS) s->l1w[i] = lin1_w[i];
    if (t < 256) s->w1s[t] = conv1_w[t];
    if (t < 32) s->c1b[t] = conv1_b[t];
    if (t < 64) s->c2b[t] = conv2_b[t];
    if (t >= 64 && t < 96) s->l1b[t - 64] = lin1_b[t - 64];
    if (t >= 96 && t < 128) s->l2w[t - 96] = lin2_w[t - 96];
    if (t == 128) s->l2b[0] = lin2_b[0];
    __syncthreads();

    // E_CNN even, base even => e = base + sub always < E_CNN: uniform loop count
    for (int base = blockIdx.x * 2; base < E_CNN; base += gridDim.x * 2) {
        int e = base + sub;
        int n0, n1;
        if (e < SL_E) {
            n0 = sl_pos[e];
            n1 = sl_pos[SL_E + e];
        } else {
            n0 = sl_neg[e - SL_E];
            n1 = sl_neg[e];
        }

        // ---- phase 1: gather image [2][14][16] via float4 ----
        if (wt < 112) {
            int c = wt / 56;
            int rem = wt - c * 56;
            int k = rem >> 2;
            int q = (rem & 3) << 2;
            int node = c ? n1 : n0;
            float4 v = *(const float4*)&g_emb[(c_slot[k] * N_NODES + node) * H2 + q];
            *(float4*)&s->img[sub][c * 224 + k * 16 + q] = v;
        }
        __syncthreads();

        // ---- phase 2: conv1 + maxpool fused -> pooled [32][6][7] ----
        const float* img = s->img[sub];
        for (int idx = wt; idx < 32 * 6 * 7; idx += 128) {
            int o = idx / 42;
            int rem = idx - o * 42;
            int y = rem / 7;
            int xx = rem - y * 7;
            const float* wv = &s->w1s[o * 8];
            float w0 = wv[0], w1 = wv[1], w2 = wv[2], w3 = wv[3];
            float w4 = wv[4], w5 = wv[5], w6 = wv[6], w7 = wv[7];
            float bb = s->c1b[o];
            float m = -1e30f;
#pragma unroll
            for (int ii = 0; ii < 2; ii++) {
#pragma unroll
                for (int jj = 0; jj < 2; jj++) {
                    int i = 2 * y + ii, j = 2 * xx + jj;
                    const float* i0p = &img[i * 16 + j];
                    const float* i1p = &img[224 + i * 16 + j];
                    float v = bb + w0 * i0p[0] + w1 * i0p[1] + w2 * i0p[16] + w3 * i0p[17] +
                              w4 * i1p[0] + w5 * i1p[1] + w6 * i1p[16] + w7 * i1p[17];
                    m = fmaxf(m, v);
                }
            }
            s->pooled[sub][o * 48 + y * 8 + xx] = m;
        }
        __syncthreads();

        // ---- phase 3: conv2 (f32x2, only the 4x4 region surviving maxpool2) ----
        {
            int o = wt >> 1, half = wt & 1, i0 = half * 2;
            float bb = s->c2b[o];
            // acc2[j] = {out[i0][j], out[i0+1][j]}, j = 0..3 (j=4 is pooled away)
            u64t acc2[4];
            u64t bb2 = pk2(bb, bb);
#pragma unroll
            for (int j = 0; j < 4; j++) acc2[j] = bb2;
            const float* pooled = s->pooled[sub];
            for (int c = 0; c < 32; c++) {
                // rows i0 .. i0+3, cols 0..7 (7 = pad, unused)
                float4 r4[4][2];
                const float* p = &pooled[c * 48 + i0 * 8];
#pragma unroll
                for (int a = 0; a < 4; a++) {
                    r4[a][0] = *(const float4*)&p[a * 8];
                    r4[a][1] = *(const float4*)&p[a * 8 + 4];
                }
                float r[4][6];
#pragma unroll
                for (int a = 0; a < 4; a++) {
                    r[a][0] = r4[a][0].x; r[a][1] = r4[a][0].y; r[a][2] = r4[a][0].z;
                    r[a][3] = r4[a][0].w; r[a][4] = r4[a][1].x; r[a][5] = r4[a][1].y;
                }
                const float* wp = &s->w2s[c * 9 * 64 + o];
#pragma unroll
                for (int di = 0; di < 3; di++) {
                    // vertical pairs for rows (di, di+1), cols 0..5
                    u64t pr[6];
#pragma unroll
                    for (int b = 0; b < 6; b++) pr[b] = pk2(r[di][b], r[di + 1][b]);
#pragma unroll
                    for (int dj = 0; dj < 3; dj++) {
                        float w = wp[(di * 3 + dj) * 64];
                        u64t ww = pk2(w, w);
#pragma unroll
                        for (int j = 0; j < 4; j++)
                            acc2[j] = fma2(pr[dj + j], ww, acc2[j]);
                    }
                }
            }
            float m = -1e30f;
#pragma unroll
            for (int j = 0; j < 4; j++) {
                float2 f = upk2(acc2[j]);
                m = fmaxf(m, fmaxf(f.x, f.y));
            }
            s->red[sub][wt] = m;
        }
        __syncthreads();
        if (wt < 64) s->feats[sub][wt] = fmaxf(s->red[sub][2 * wt], s->red[sub][2 * wt + 1]);
        __syncthreads();
        if (wt < 32) {
            float acc = s->l1b[wt];
            const float* fp = s->feats[sub];
#pragma unroll 16
            for (int d = 0; d < 64; d++) acc += fp[d] * s->l1w[wt * 64 + d];
            s->h2s[sub][wt] = fmaxf(acc, 0.f);
        }
        __syncthreads();
        if (wt == 0) {
            float y = s->l2b[0];
#pragma unroll
            for (int d = 0; d < 32; d++) y += s->h2s[sub][d] * s->l2w[d];
            out[e] = 1.f / (1.f + expf(-y));
        }
        __syncthreads();
    }
}

// -------- launch --------
extern "C" void kernel_launch(void* const* d_in, const int* in_sizes, int n_in,
                              void* d_out, int out_size) {
    const float* x       = (const float*)d_in[0];
    const int*   sl_pos  = (const int*)d_in[1];
    const int*   sl_neg  = (const int*)d_in[2];
    const int*   kg_edges= (const int*)d_in[3];
    const float* Wsl1    = (const float*)d_in[4];
    const float* bsl1    = (const float*)d_in[5];
    const float* Wsl2    = (const float*)d_in[6];
    const float* bsl2    = (const float*)d_in[7];
    const float* Wkg1    = (const float*)d_in[8];
    const float* bkg1    = (const float*)d_in[9];
    const float* Wkg2    = (const float*)d_in[10];
    const float* bkg2    = (const float*)d_in[11];
    const float* conv1_w = (const float*)d_in[12];
    const float* conv1_b = (const float*)d_in[13];
    const float* conv2_w = (const float*)d_in[14];
    const float* conv2_b = (const float*)d_in[15];
    const float* lin1_w  = (const float*)d_in[16];
    const float* lin1_b  = (const float*)d_in[17];
    const float* lin2_w  = (const float*)d_in[18];
    const float* lin2_b  = (const float*)d_in[19];
    float* out = (float*)d_out;

    void *p_agg1, *p_agg2, *p_deg;
    cudaGetSymbolAddress(&p_agg1, g_agg1);
    cudaGetSymbolAddress(&p_agg2, g_agg2);
    cudaGetSymbolAddress(&p_deg, g_deg);
    cudaMemsetAsync(p_agg1, 0, sizeof(float) * NG * N_NODES * H1);
    cudaMemsetAsync(p_agg2, 0, sizeof(float) * NG * N_NODES * H2);
    cudaMemsetAsync(p_deg, 0, sizeof(int) * NG * N_NODES);

    degree_kernel<<<(TOT_EDGES + 255) / 256, 256>>>(sl_pos, kg_edges);
    dis_kernel<<<(NG * N_NODES + 255) / 256, 256>>>();
    gemm1_kernel<<<dim3((N_NODES + 63) / 64, NG), 256>>>(x, Wsl1, Wkg1);
    scatter1_kernel<<<(TOT_EDGES + 7) / 8, 256>>>(sl_pos, kg_edges);
    gemm2_kernel<<<dim3((N_NODES + 15) / 16, NG), 256>>>(Wsl2, Wkg2, bsl1, bkg1);
    scatter2_kernel<<<(TOT_EDGES + 63) / 64, 256>>>(sl_pos, kg_edges);
    emb_kernel<<<(NG * N_NODES * H2 + 255) / 256, 256>>>(bsl2, bkg2);

    cudaFuncSetAttribute(cnn_kernel, cudaFuncAttributeMaxDynamicSharedMemorySize,
                         (int)sizeof(CnnSmem));
    cnn_kernel<<<296, CNN_THREADS, sizeof(CnnSmem)>>>(
        sl_pos, sl_neg, conv1_w, conv1_b, conv2_w, conv2_b,
        lin1_w, lin1_b, lin2_w, lin2_b, out);
}

// round 7
// speedup vs baseline: 1.2538x; 1.0897x over previous
#include <cuda_runtime.h>
#include <math.h>

#define N_NODES 20000
#define D_IN 256
#define H1 128
#define H2 16
#define KG_E 200000
#define SL_E 20000
#define NG 8
#define TOT_EDGES (SL_E + 7 * KG_E)
#define E_CNN 40000
#define CNN_THREADS 256
#define NB (NG * N_NODES)                      // 160000 bins
#define SCAN_BS 1024
#define SCAN_NBLK ((NB + SCAN_BS - 1) / SCAN_BS)  // 157

// -------- packed f32x2 helpers (sm_100a) --------
typedef unsigned long long u64t;
__device__ __forceinline__ u64t pk2(float lo, float hi) {
    u64t r;
    asm("mov.b64 %0, {%1, %2};" : "=l"(r) : "r"(__float_as_uint(lo)), "r"(__float_as_uint(hi)));
    return r;
}
__device__ __forceinline__ u64t fma2(u64t a, u64t b, u64t c) {
    u64t d;
    asm("fma.rn.f32x2 %0, %1, %2, %3;" : "=l"(d) : "l"(a), "l"(b), "l"(c));
    return d;
}
__device__ __forceinline__ float2 upk2(u64t v) {
    unsigned int lo, hi;
    asm("mov.b64 {%0, %1}, %2;" : "=r"(lo), "=r"(hi) : "l"(v));
    return make_float2(__uint_as_float(lo), __uint_as_float(hi));
}

// -------- scratch (device globals; no allocation allowed) --------
__device__ float g_xw1[NG * N_NODES * H1];
__device__ float g_agg1[NG * N_NODES * H1];
__device__ float g_xw2[NG * N_NODES * H2];
__device__ float g_agg2[NG * N_NODES * H2];
__device__ float g_emb[NG * N_NODES * H2];
__device__ int   g_deg[NB];
__device__ float g_dis[NB];
__device__ int   g_off[NB + 1];   // CSR exclusive offsets
__device__ int   g_cur[NB];       // fill cursors
__device__ int   g_csr[TOT_EDGES];// CSR src indices
__device__ int   g_bsum[SCAN_NBLK];

// emb_all row k -> slot in g_emb (slot0=sl, 1..7 = ppi,reactome,corum,go_f,go_c,go_p,kegg)
__constant__ int c_slot[14] = {0, 2, 0, 7, 0, 4, 0, 3, 0, 5, 0, 6, 0, 1};

__device__ __forceinline__ void decode_edge(int eid, const int* __restrict__ sl_pos,
                                            const int* __restrict__ kg_edges,
                                            int& g, int& src, int& dst) {
    if (eid < SL_E) {
        g = 0;
        src = sl_pos[eid];
        dst = sl_pos[SL_E + eid];
    } else {
        int r = eid - SL_E;
        int gg = r / KG_E;
        int i = r - gg * KG_E;
        g = gg + 1;
        const int* base = kg_edges + gg * 2 * KG_E;
        src = base[i];
        dst = base[KG_E + i];
    }
}

// -------- degree histogram --------
__global__ void degree_kernel(const int* __restrict__ sl_pos, const int* __restrict__ kg_edges) {
    int e = blockIdx.x * blockDim.x + threadIdx.x;
    if (e >= TOT_EDGES) return;
    int g, dst;
    if (e < SL_E) {
        g = 0;
        dst = sl_pos[SL_E + e];
    } else {
        int r = e - SL_E;
        int gg = r / KG_E;
        int i = r - gg * KG_E;
        g = gg + 1;
        dst = kg_edges[gg * 2 * KG_E + KG_E + i];
    }
    atomicAdd(&g_deg[g * N_NODES + dst], 1);
}

__global__ void dis_kernel() {
    int i = blockIdx.x * blockDim.x + threadIdx.x;
    if (i < NB) g_dis[i] = rsqrtf((float)(g_deg[i] + 1));
}

// -------- exclusive scan of g_deg -> g_off (3 kernels) --------
__global__ void scan_local_kernel() {
    __shared__ int wsum[32];
    int i = blockIdx.x * SCAN_BS + threadIdx.x;
    int lane = threadIdx.x & 31, wid = threadIdx.x >> 5;
    int v = (i < NB) ? g_deg[i] : 0;
    int x = v;
#pragma unroll
    for (int d = 1; d < 32; d <<= 1) {
        int y = __shfl_up_sync(0xffffffffu, x, d);
        if (lane >= d) x += y;
    }
    if (lane == 31) wsum[wid] = x;
    __syncthreads();
    if (wid == 0) {
        int s = wsum[lane];
        int t2 = s;
#pragma unroll
        for (int d = 1; d < 32; d <<= 1) {
            int y = __shfl_up_sync(0xffffffffu, t2, d);
            if (lane >= d) t2 += y;
        }
        wsum[lane] = t2 - s;  // exclusive warp base
        if (lane == 31) g_bsum[blockIdx.x] = t2;  // block total
    }
    __syncthreads();
    if (i < NB) g_off[i] = x - v + wsum[wid];  // block-local exclusive
}

__global__ void scan_top_kernel() {  // 1 block, 256 threads, SCAN_NBLK<=256
    __shared__ int wsum[8];
    int lane = threadIdx.x & 31, wid = threadIdx.x >> 5;
    int v = (threadIdx.x < SCAN_NBLK) ? g_bsum[threadIdx.x] : 0;
    int x = v;
#pragma unroll
    for (int d = 1; d < 32; d <<= 1) {
        int y = __shfl_up_sync(0xffffffffu, x, d);
        if (lane >= d) x += y;
    }
    if (lane == 31) wsum[wid] = x;
    __syncthreads();
    if (wid == 0) {
        int s = (lane < 8) ? wsum[lane] : 0;
        int t2 = s;
#pragma unroll
        for (int d = 1; d < 32; d <<= 1) {
            int y = __shfl_up_sync(0xffffffffu, t2, d);
            if (lane >= d) t2 += y;
        }
        if (lane < 8) wsum[lane] = t2 - s;
    }
    __syncthreads();
    if (threadIdx.x < SCAN_NBLK) g_bsum[threadIdx.x] = x - v + wsum[wid];
}

__global__ void scan_add_kernel() {
    int i = blockIdx.x * SCAN_BS + threadIdx.x;
    if (i < NB) {
        int o = g_off[i] + g_bsum[blockIdx.x];
        g_off[i] = o;
        g_cur[i] = o;
        if (i == NB - 1) g_off[NB] = o + g_deg[i];
    }
}

// -------- CSR fill --------
__global__ void fill_csr_kernel(const int* __restrict__ sl_pos, const int* __restrict__ kg_edges) {
    int e = blockIdx.x * blockDim.x + threadIdx.x;
    if (e >= TOT_EDGES) return;
    int g, src, dst;
    decode_edge(e, sl_pos, kg_edges, g, src, dst);
    int pos = atomicAdd(&g_cur[g * N_NODES + dst], 1);
    g_csr[pos] = src;
}

// -------- GEMM1: xw1[g] = x @ W1_g  (packed f32x2, transposed A smem) --------
__global__ void gemm1_kernel(const float* __restrict__ x,
                             const float* __restrict__ Wsl1,
                             const float* __restrict__ Wkg1) {
    __shared__ float As2[16][64];   // [k][row]
    __shared__ float Bs[16][128];
    int g = blockIdx.y;
    const float* B = (g == 0) ? Wsl1 : (Wkg1 + (g - 1) * D_IN * H1);
    int row0 = blockIdx.x * 64;
    int t = threadIdx.x;
    int tx = t & 31, ty = t >> 5;
    int ty8 = ty << 3;
    u64t acc2[8][2];
#pragma unroll
    for (int r = 0; r < 8; r++) {
        acc2[r][0] = 0ull;
        acc2[r][1] = 0ull;
    }

    int ai = t >> 2, aq = (t & 3) << 2;
    for (int kb = 0; kb < D_IN; kb += 16) {
        int arow = row0 + ai;
        float4 av = make_float4(0.f, 0.f, 0.f, 0.f);
        if (arow < N_NODES) av = *(const float4*)&x[arow * D_IN + kb + aq];
        As2[aq + 0][ai] = av.x;
        As2[aq + 1][ai] = av.y;
        As2[aq + 2][ai] = av.z;
        As2[aq + 3][ai] = av.w;
#pragma unroll
        for (int l = 0; l < 2; l++) {
            int lin = t + l * 256;
            int bk = lin >> 5, bq = (lin & 31) << 2;
            *(float4*)&Bs[bk][bq] = *(const float4*)&B[(kb + bk) * H1 + bq];
        }
        __syncthreads();
#pragma unroll
        for (int k = 0; k < 16; k++) {
            float4 alo = *(float4*)&As2[k][ty8];
            float4 ahi = *(float4*)&As2[k][ty8 + 4];
            float4 b = *(float4*)&Bs[k][tx << 2];
            u64t b01 = pk2(b.x, b.y);
            u64t b23 = pk2(b.z, b.w);
            float ar[8] = {alo.x, alo.y, alo.z, alo.w, ahi.x, ahi.y, ahi.z, ahi.w};
#pragma unroll
            for (int r = 0; r < 8; r++) {
                u64t aa = pk2(ar[r], ar[r]);
                acc2[r][0] = fma2(aa, b01, acc2[r][0]);
                acc2[r][1] = fma2(aa, b23, acc2[r][1]);
            }
        }
        __syncthreads();
    }
#pragma unroll
    for (int r = 0; r < 8; r++) {
        int row = row0 + ty8 + r;
        if (row < N_NODES) {
            float2 lo = upk2(acc2[r][0]);
            float2 hi = upk2(acc2[r][1]);
            *(float4*)&g_xw1[(g * N_NODES + row) * H1 + (tx << 2)] =
                make_float4(lo.x, lo.y, hi.x, hi.y);
        }
    }
}

// -------- gather layer1: agg1[bin] = sum over CSR srcs (warp per bin, no atomics) --------
__global__ void gather1_kernel() {
    int warp = (blockIdx.x * blockDim.x + threadIdx.x) >> 5;
    if (warp >= NB) return;
    int lane = threadIdx.x & 31;
    int g = warp / N_NODES;
    int beg = g_off[warp], end = g_off[warp + 1];
    float disd = g_dis[warp];
    int gbase = g * N_NODES;
    float4 acc = make_float4(0.f, 0.f, 0.f, 0.f);
    int j = beg;
    for (; j + 1 < end; j += 2) {
        int s0 = g_csr[j], s1 = g_csr[j + 1];
        float n0 = disd * g_dis[gbase + s0];
        float n1 = disd * g_dis[gbase + s1];
        const float4 v0 = *(const float4*)&g_xw1[(gbase + s0) * H1 + (lane << 2)];
        const float4 v1 = *(const float4*)&g_xw1[(gbase + s1) * H1 + (lane << 2)];
        acc.x += n0 * v0.x + n1 * v1.x;
        acc.y += n0 * v0.y + n1 * v1.y;
        acc.z += n0 * v0.z + n1 * v1.z;
        acc.w += n0 * v0.w + n1 * v1.w;
    }
    if (j < end) {
        int s0 = g_csr[j];
        float n0 = disd * g_dis[gbase + s0];
        const float4 v0 = *(const float4*)&g_xw1[(gbase + s0) * H1 + (lane << 2)];
        acc.x += n0 * v0.x;
        acc.y += n0 * v0.y;
        acc.z += n0 * v0.z;
        acc.w += n0 * v0.w;
    }
    *(float4*)&g_agg1[warp * H1 + (lane << 2)] = acc;
}

// -------- h = relu(agg1 + dis^2*xw1 + b1); xw2 = h @ W2 --------
__global__ void gemm2_kernel(const float* __restrict__ Wsl2, const float* __restrict__ Wkg2,
                             const float* __restrict__ bsl1, const float* __restrict__ bkg1) {
    __shared__ float hs[16 * 128];
    __shared__ float w2s[128 * 16];
    int g = blockIdx.y;
    int n0 = blockIdx.x * 16;
    const float* W2 = (g == 0) ? Wsl2 : (Wkg2 + (g - 1) * H1 * H2);
    const float* b1 = (g == 0) ? bsl1 : (bkg1 + (g - 1) * H1);
    int t = threadIdx.x;
    for (int idx = t; idx < H1 * H2; idx += 256) w2s[idx] = W2[idx];
    for (int idx = t; idx < 16 * H1; idx += 256) {
        int r = idx >> 7, k = idx & 127;
        int n = n0 + r;
        float h = 0.f;
        if (n < N_NODES) {
            float dis = g_dis[g * N_NODES + n];
            int base = (g * N_NODES + n) * H1 + k;
            h = g_agg1[base] + dis * dis * g_xw1[base] + b1[k];
            h = fmaxf(h, 0.f);
        }
        hs[idx] = h;
    }
    __syncthreads();
    int r = t >> 4, j = t & 15;
    int n = n0 + r;
    if (n < N_NODES) {
        float acc = 0.f;
#pragma unroll 8
        for (int k = 0; k < H1; k++) acc += hs[r * 128 + k] * w2s[k * 16 + j];
        g_xw2[(g * N_NODES + n) * H2 + j] = acc;
    }
}

// -------- gather layer2 (thread per bin, 16 feats) --------
__global__ void gather2_kernel() {
    int bin = blockIdx.x * blockDim.x + threadIdx.x;
    if (bin >= NB) return;
    int g = bin / N_NODES;
    int beg = g_off[bin], end = g_off[bin + 1];
    float disd = g_dis[bin];
    int gbase = g * N_NODES;
    float4 a0 = make_float4(0.f, 0.f, 0.f, 0.f);
    float4 a1 = a0, a2 = a0, a3 = a0;
    for (int j = beg; j < end; j++) {
        int src = g_csr[j];
        float nrm = disd * g_dis[gbase + src];
        const float4* row = (const float4*)&g_xw2[(gbase + src) * H2];
        float4 v0 = row[0], v1 = row[1], v2 = row[2], v3 = row[3];
        a0.x += nrm * v0.x; a0.y += nrm * v0.y; a0.z += nrm * v0.z; a0.w += nrm * v0.w;
        a1.x += nrm * v1.x; a1.y += nrm * v1.y; a1.z += nrm * v1.z; a1.w += nrm * v1.w;
        a2.x += nrm * v2.x; a2.y += nrm * v2.y; a2.z += nrm * v2.z; a2.w += nrm * v2.w;
        a3.x += nrm * v3.x; a3.y += nrm * v3.y; a3.z += nrm * v3.z; a3.w += nrm * v3.w;
    }
    float4* o = (float4*)&g_agg2[bin * H2];
    o[0] = a0; o[1] = a1; o[2] = a2; o[3] = a3;
}

// -------- emb = agg2 + dis^2*xw2 + b2 --------
__global__ void emb_kernel(const float* __restrict__ bsl2, const float* __restrict__ bkg2) {
    int idx = blockIdx.x * blockDim.x + threadIdx.x;
    if (idx >= NG * N_NODES * H2) return;
    int g = idx / (N_NODES * H2);
    int rem = idx - g * (N_NODES * H2);
    int n = rem >> 4;
    int d = rem & 15;
    float dis = g_dis[g * N_NODES + n];
    float b = (g == 0) ? bsl2[d] : bkg2[(g - 1) * 16 + d];
    g_emb[idx] = g_agg2[idx] + dis * dis * g_xw2[idx] + b;
}

// -------- per-edge CNN: 2 edges/block, named barriers per sub, shfl epilogue --------
struct CnnSmem {
    float w2s[32 * 9 * 64];   // 18432 floats, offset 0
    float l1w[32 * 64];       // 2048
    float w1s[32 * 8];        // 256
    float c1b[32];
    float c2b[64];
    float l1b[32];
    float l2w[32];
    float l2b[4];             // padded: keeps img/pooled 16B-aligned
    float img[2][2 * 14 * 16];    // 16B-aligned
    float pooled[2][32 * 6 * 8];  // 16B-aligned
    float feats[2][64];
};

#define BARSYNC(id) asm volatile("bar.sync %0, 128;" :: "r"(id) : "memory")

__global__ __launch_bounds__(CNN_THREADS, 2)
void cnn_kernel(const int* __restrict__ sl_pos, const int* __restrict__ sl_neg,
                const float* __restrict__ conv1_w, const float* __restrict__ conv1_b,
                const float* __restrict__ conv2_w, const float* __restrict__ conv2_b,
                const float* __restrict__ lin1_w, const float* __restrict__ lin1_b,
                const float* __restrict__ lin2_w, const float* __restrict__ lin2_b,
                float* __restrict__ out) {
    extern __shared__ __align__(16) char smem_raw[];
    CnnSmem* s = reinterpret_cast<CnnSmem*>(smem_raw);
    int t = threadIdx.x;
    int sub = t >> 7;       // which edge slot (0/1)
    int wt = t & 127;       // thread id within sub-block
    int barid = sub + 1;    // named barrier per sub

    // ---- load all weights once per block ----
    for (int i = t; i < 64 * 32 * 9; i += CNN_THREADS) {
        int o = i / 288;
        int rem = i - o * 288;  // c*9 + k
        s->w2s[rem * 64 + o] = conv2_w[i];
    }
    for (int i = t; i < 32 * 64; i += CNN_THREADS) s->l1w[i] = lin1_w[i];
    if (t < 256) s->w1s[t] = conv1_w[t];
    if (t < 32) s->c1b[t] = conv1_b[t];
    if (t < 64) s->c2b[t] = conv2_b[t];
    if (t >= 64 && t < 96) s->l1b[t - 64] = lin1_b[t - 64];
    if (t >= 96 && t < 128) s->l2w[t - 96] = lin2_w[t - 96];
    if (t == 128) s->l2b[0] = lin2_b[0];
    __syncthreads();

    // E_CNN even, base even => e = base + sub always < E_CNN: uniform loop count
    for (int base = blockIdx.x * 2; base < E_CNN; base += gridDim.x * 2) {
        int e = base + sub;
        int n0, n1;
        if (e < SL_E) {
            n0 = sl_pos[e];
            n1 = sl_pos[SL_E + e];
        } else {
            n0 = sl_neg[e - SL_E];
            n1 = sl_neg[e];
        }

        // ---- phase 1: gather image [2][14][16] via float4 ----
        if (wt < 112) {
            int c = wt / 56;
            int rem = wt - c * 56;
            int k = rem >> 2;
            int q = (rem & 3) << 2;
            int node = c ? n1 : n0;
            float4 v = *(const float4*)&g_emb[(c_slot[k] * N_NODES + node) * H2 + q];
            *(float4*)&s->img[sub][c * 224 + k * 16 + q] = v;
        }
        BARSYNC(barid);

        // ---- phase 2: conv1 + maxpool fused -> pooled [32][6][7] ----
        const float* img = s->img[sub];
        for (int idx = wt; idx < 32 * 6 * 7; idx += 128) {
            int o = idx / 42;
            int rem = idx - o * 42;
            int y = rem / 7;
            int xx = rem - y * 7;
            const float* wv = &s->w1s[o * 8];
            float w0 = wv[0], w1 = wv[1], w2 = wv[2], w3 = wv[3];
            float w4 = wv[4], w5 = wv[5], w6 = wv[6], w7 = wv[7];
            float bb = s->c1b[o];
            float m = -1e30f;
#pragma unroll
            for (int ii = 0; ii < 2; ii++) {
#pragma unroll
                for (int jj = 0; jj < 2; jj++) {
                    int i = 2 * y + ii, j = 2 * xx + jj;
                    const float* i0p = &img[i * 16 + j];
                    const float* i1p = &img[224 + i * 16 + j];
                    float v = bb + w0 * i0p[0] + w1 * i0p[1] + w2 * i0p[16] + w3 * i0p[17] +
                              w4 * i1p[0] + w5 * i1p[1] + w6 * i1p[16] + w7 * i1p[17];
                    m = fmaxf(m, v);
                }
            }
            s->pooled[sub][o * 48 + y * 8 + xx] = m;
        }
        BARSYNC(barid);

        // ---- phase 3: conv2 (f32x2, 4x4 surviving region) + pair-max via shfl ----
        {
            int o = wt >> 1, half = wt & 1, i0 = half * 2;
            float bb = s->c2b[o];
            u64t acc2[4];
            u64t bb2 = pk2(bb, bb);
#pragma unroll
            for (int j = 0; j < 4; j++) acc2[j] = bb2;
            const float* pooled = s->pooled[sub];
            for (int c = 0; c < 32; c++) {
                float4 r4[4][2];
                const float* p = &pooled[c * 48 + i0 * 8];
#pragma unroll
                for (int a = 0; a < 4; a++) {
                    r4[a][0] = *(const float4*)&p[a * 8];
                    r4[a][1] = *(const float4*)&p[a * 8 + 4];
                }
                float r[4][6];
#pragma unroll
                for (int a = 0; a < 4; a++) {
                    r[a][0] = r4[a][0].x; r[a][1] = r4[a][0].y; r[a][2] = r4[a][0].z;
                    r[a][3] = r4[a][0].w; r[a][4] = r4[a][1].x; r[a][5] = r4[a][1].y;
                }
                const float* wp = &s->w2s[c * 9 * 64 + o];
#pragma unroll
                for (int di = 0; di < 3; di++) {
                    u64t pr[6];
#pragma unroll
                    for (int b = 0; b < 6; b++) pr[b] = pk2(r[di][b], r[di + 1][b]);
#pragma unroll
                    for (int dj = 0; dj < 3; dj++) {
                        float w = wp[(di * 3 + dj) * 64];
                        u64t ww = pk2(w, w);
#pragma unroll
                        for (int j = 0; j < 4; j++)
                            acc2[j] = fma2(pr[dj + j], ww, acc2[j]);
                    }
                }
            }
            float m = -1e30f;
#pragma unroll
            for (int j = 0; j < 4; j++) {
                float2 f = upk2(acc2[j]);
                m = fmaxf(m, fmaxf(f.x, f.y));
            }
            // combine halves: even thread (half=0) ends with feats[o]
            float mo = fmaxf(m, __shfl_down_sync(0xffffffffu, m, 1));
            if ((wt & 1) == 0) s->feats[sub][o] = mo;
        }
        BARSYNC(barid);

        // ---- epilogue: warp 0 of sub only (overlaps other warps' next gather) ----
        if (wt < 32) {
            float acc = s->l1b[wt];
            const float* fp = s->feats[sub];
#pragma unroll 16
            for (int d = 0; d < 64; d++) acc += fp[d] * s->l1w[wt * 64 + d];
            float h = fmaxf(acc, 0.f);
            float p = h * s->l2w[wt];
#pragma unroll
            for (int off = 16; off; off >>= 1) p += __shfl_down_sync(0xffffffffu, p, off);
            if (wt == 0) out[e] = 1.f / (1.f + expf(-(p + s->l2b[0])));
        }
        // no barrier here: next iteration's BARSYNC after gather protects img;
        // feats[sub] is re-written only after the NEXT phase-3, which every
        // warp (incl. warp 0) reaches only after passing two more barriers.
    }
}

// -------- launch --------
extern "C" void kernel_launch(void* const* d_in, const int* in_sizes, int n_in,
                              void* d_out, int out_size) {
    const float* x       = (const float*)d_in[0];
    const int*   sl_pos  = (const int*)d_in[1];
    const int*   sl_neg  = (const int*)d_in[2];
    const int*   kg_edges= (const int*)d_in[3];
    const float* Wsl1    = (const float*)d_in[4];
    const float* bsl1    = (const float*)d_in[5];
    const float* Wsl2    = (const float*)d_in[6];
    const float* bsl2    = (const float*)d_in[7];
    const float* Wkg1    = (const float*)d_in[8];
    const float* bkg1    = (const float*)d_in[9];
    const float* Wkg2    = (const float*)d_in[10];
    const float* bkg2    = (const float*)d_in[11];
    const float* conv1_w = (const float*)d_in[12];
    const float* conv1_b = (const float*)d_in[13];
    const float* conv2_w = (const float*)d_in[14];
    const float* conv2_b = (const float*)d_in[15];
    const float* lin1_w  = (const float*)d_in[16];
    const float* lin1_b  = (const float*)d_in[17];
    const float* lin2_w  = (const float*)d_in[18];
    const float* lin2_b  = (const float*)d_in[19];
    float* out = (float*)d_out;

    void* p_deg;
    cudaGetSymbolAddress(&p_deg, g_deg);
    cudaMemsetAsync(p_deg, 0, sizeof(int) * NB);

    degree_kernel<<<(TOT_EDGES + 255) / 256, 256>>>(sl_pos, kg_edges);
    dis_kernel<<<(NB + 255) / 256, 256>>>();
    scan_local_kernel<<<SCAN_NBLK, SCAN_BS>>>();
    scan_top_kernel<<<1, 256>>>();
    scan_add_kernel<<<SCAN_NBLK, SCAN_BS>>>();
    fill_csr_kernel<<<(TOT_EDGES + 255) / 256, 256>>>(sl_pos, kg_edges);
    gemm1_kernel<<<dim3((N_NODES + 63) / 64, NG), 256>>>(x, Wsl1, Wkg1);
    gather1_kernel<<<(NB * 32 + 255) / 256, 256>>>();
    gemm2_kernel<<<dim3((N_NODES + 15) / 16, NG), 256>>>(Wsl2, Wkg2, bsl1, bkg1);
    gather2_kernel<<<(NB + 255) / 256, 256>>>();
    emb_kernel<<<(NG * N_NODES * H2 + 255) / 256, 256>>>(bsl2, bkg2);

    cudaFuncSetAttribute(cnn_kernel, cudaFuncAttributeMaxDynamicSharedMemorySize,
                         (int)sizeof(CnnSmem));
    cnn_kernel<<<296, CNN_THREADS, sizeof(CnnSmem)>>>(
        sl_pos, sl_neg, conv1_w, conv1_b, conv2_w, conv2_b,
        lin1_w, lin1_b, lin2_w, lin2_b, out);
}

// round 8
// speedup vs baseline: 1.4173x; 1.1304x over previous
#include <cuda_runtime.h>
#include <math.h>

#define N_NODES 20000
#define D_IN 256
#define H1 128
#define H2 16
#define KG_E 200000
#define SL_E 20000
#define NG 8
#define TOT_EDGES (SL_E + 7 * KG_E)
#define E_CNN 40000
#define CNN_SUBS 5
#define CNN_THREADS (128 * CNN_SUBS)   // 640
#define NB (NG * N_NODES)              // 160000 bins
#define SCAN_BS 1024
#define SCAN_NBLK ((NB + SCAN_BS - 1) / SCAN_BS)  // 157

// -------- packed f32x2 helpers (sm_100a) --------
typedef unsigned long long u64t;
__device__ __forceinline__ u64t pk2(float lo, float hi) {
    u64t r;
    asm("mov.b64 %0, {%1, %2};" : "=l"(r) : "r"(__float_as_uint(lo)), "r"(__float_as_uint(hi)));
    return r;
}
__device__ __forceinline__ u64t fma2(u64t a, u64t b, u64t c) {
    u64t d;
    asm("fma.rn.f32x2 %0, %1, %2, %3;" : "=l"(d) : "l"(a), "l"(b), "l"(c));
    return d;
}
__device__ __forceinline__ float2 upk2(u64t v) {
    unsigned int lo, hi;
    asm("mov.b64 {%0, %1}, %2;" : "=r"(lo), "=r"(hi) : "l"(v));
    return make_float2(__uint_as_float(lo), __uint_as_float(hi));
}

// -------- scratch (device globals; no allocation allowed) --------
__device__ float g_xw1[NG * N_NODES * H1];
__device__ float g_h[NG * N_NODES * H1];     // relu(agg1 + self + b1)
__device__ float g_xw2[NG * N_NODES * H2];
__device__ float g_emb[NG * N_NODES * H2];
__device__ int   g_deg[NB];
__device__ float g_dis[NB];
__device__ int   g_off[NB + 1];
__device__ int   g_cur[NB];
__device__ int   g_csr[TOT_EDGES];
__device__ int   g_bsum[SCAN_NBLK];

// emb_all row k -> slot in g_emb (slot0=sl, 1..7 = ppi,reactome,corum,go_f,go_c,go_p,kegg)
__constant__ int c_slot[14] = {0, 2, 0, 7, 0, 4, 0, 3, 0, 5, 0, 6, 0, 1};

__device__ __forceinline__ void decode_edge(int eid, const int* __restrict__ sl_pos,
                                            const int* __restrict__ kg_edges,
                                            int& g, int& src, int& dst) {
    if (eid < SL_E) {
        g = 0;
        src = sl_pos[eid];
        dst = sl_pos[SL_E + eid];
    } else {
        int r = eid - SL_E;
        int gg = r / KG_E;
        int i = r - gg * KG_E;
        g = gg + 1;
        const int* base = kg_edges + gg * 2 * KG_E;
        src = base[i];
        dst = base[KG_E + i];
    }
}

// -------- degree histogram --------
__global__ void degree_kernel(const int* __restrict__ sl_pos, const int* __restrict__ kg_edges) {
    int e = blockIdx.x * blockDim.x + threadIdx.x;
    if (e >= TOT_EDGES) return;
    int g, dst;
    if (e < SL_E) {
        g = 0;
        dst = sl_pos[SL_E + e];
    } else {
        int r = e - SL_E;
        int gg = r / KG_E;
        int i = r - gg * KG_E;
        g = gg + 1;
        dst = kg_edges[gg * 2 * KG_E + KG_E + i];
    }
    atomicAdd(&g_deg[g * N_NODES + dst], 1);
}

__global__ void dis_kernel() {
    int i = blockIdx.x * blockDim.x + threadIdx.x;
    if (i < NB) g_dis[i] = rsqrtf((float)(g_deg[i] + 1));
}

// -------- exclusive scan of g_deg -> g_off --------
__global__ void scan_local_kernel() {
    __shared__ int wsum[32];
    int i = blockIdx.x * SCAN_BS + threadIdx.x;
    int lane = threadIdx.x & 31, wid = threadIdx.x >> 5;
    int v = (i < NB) ? g_deg[i] : 0;
    int x = v;
#pragma unroll
    for (int d = 1; d < 32; d <<= 1) {
        int y = __shfl_up_sync(0xffffffffu, x, d);
        if (lane >= d) x += y;
    }
    if (lane == 31) wsum[wid] = x;
    __syncthreads();
    if (wid == 0) {
        int s = wsum[lane];
        int t2 = s;
#pragma unroll
        for (int d = 1; d < 32; d <<= 1) {
            int y = __shfl_up_sync(0xffffffffu, t2, d);
            if (lane >= d) t2 += y;
        }
        wsum[lane] = t2 - s;
        if (lane == 31) g_bsum[blockIdx.x] = t2;
    }
    __syncthreads();
    if (i < NB) g_off[i] = x - v + wsum[wid];
}

__global__ void scan_top_kernel() {
    __shared__ int wsum[8];
    int lane = threadIdx.x & 31, wid = threadIdx.x >> 5;
    int v = (threadIdx.x < SCAN_NBLK) ? g_bsum[threadIdx.x] : 0;
    int x = v;
#pragma unroll
    for (int d = 1; d < 32; d <<= 1) {
        int y = __shfl_up_sync(0xffffffffu, x, d);
        if (lane >= d) x += y;
    }
    if (lane == 31) wsum[wid] = x;
    __syncthreads();
    if (wid == 0) {
        int s = (lane < 8) ? wsum[lane] : 0;
        int t2 = s;
#pragma unroll
        for (int d = 1; d < 32; d <<= 1) {
            int y = __shfl_up_sync(0xffffffffu, t2, d);
            if (lane >= d) t2 += y;
        }
        if (lane < 8) wsum[lane] = t2 - s;
    }
    __syncthreads();
    if (threadIdx.x < SCAN_NBLK) g_bsum[threadIdx.x] = x - v + wsum[wid];
}

__global__ void scan_add_kernel() {
    int i = blockIdx.x * SCAN_BS + threadIdx.x;
    if (i < NB) {
        int o = g_off[i] + g_bsum[blockIdx.x];
        g_off[i] = o;
        g_cur[i] = o;
        if (i == NB - 1) g_off[NB] = o + g_deg[i];
    }
}

// -------- CSR fill --------
__global__ void fill_csr_kernel(const int* __restrict__ sl_pos, const int* __restrict__ kg_edges) {
    int e = blockIdx.x * blockDim.x + threadIdx.x;
    if (e >= TOT_EDGES) return;
    int g, src, dst;
    decode_edge(e, sl_pos, kg_edges, g, src, dst);
    int pos = atomicAdd(&g_cur[g * N_NODES + dst], 1);
    g_csr[pos] = src;
}

// -------- GEMM1: xw1[g] = x @ W1_g  (packed f32x2, transposed A smem) --------
__global__ void gemm1_kernel(const float* __restrict__ x,
                             const float* __restrict__ Wsl1,
                             const float* __restrict__ Wkg1) {
    __shared__ float As2[16][64];   // [k][row]
    __shared__ float Bs[16][128];
    int g = blockIdx.y;
    const float* B = (g == 0) ? Wsl1 : (Wkg1 + (g - 1) * D_IN * H1);
    int row0 = blockIdx.x * 64;
    int t = threadIdx.x;
    int tx = t & 31, ty = t >> 5;
    int ty8 = ty << 3;
    u64t acc2[8][2];
#pragma unroll
    for (int r = 0; r < 8; r++) {
        acc2[r][0] = 0ull;
        acc2[r][1] = 0ull;
    }

    int ai = t >> 2, aq = (t & 3) << 2;
    for (int kb = 0; kb < D_IN; kb += 16) {
        int arow = row0 + ai;
        float4 av = make_float4(0.f, 0.f, 0.f, 0.f);
        if (arow < N_NODES) av = *(const float4*)&x[arow * D_IN + kb + aq];
        As2[aq + 0][ai] = av.x;
        As2[aq + 1][ai] = av.y;
        As2[aq + 2][ai] = av.z;
        As2[aq + 3][ai] = av.w;
#pragma unroll
        for (int l = 0; l < 2; l++) {
            int lin = t + l * 256;
            int bk = lin >> 5, bq = (lin & 31) << 2;
            *(float4*)&Bs[bk][bq] = *(const float4*)&B[(kb + bk) * H1 + bq];
        }
        __syncthreads();
#pragma unroll
        for (int k = 0; k < 16; k++) {
            float4 alo = *(float4*)&As2[k][ty8];
            float4 ahi = *(float4*)&As2[k][ty8 + 4];
            float4 b = *(float4*)&Bs[k][tx << 2];
            u64t b01 = pk2(b.x, b.y);
            u64t b23 = pk2(b.z, b.w);
            float ar[8] = {alo.x, alo.y, alo.z, alo.w, ahi.x, ahi.y, ahi.z, ahi.w};
#pragma unroll
            for (int r = 0; r < 8; r++) {
                u64t aa = pk2(ar[r], ar[r]);
                acc2[r][0] = fma2(aa, b01, acc2[r][0]);
                acc2[r][1] = fma2(aa, b23, acc2[r][1]);
            }
        }
        __syncthreads();
    }
#pragma unroll
    for (int r = 0; r < 8; r++) {
        int row = row0 + ty8 + r;
        if (row < N_NODES) {
            float2 lo = upk2(acc2[r][0]);
            float2 hi = upk2(acc2[r][1]);
            *(float4*)&g_xw1[(g * N_NODES + row) * H1 + (tx << 2)] =
                make_float4(lo.x, lo.y, hi.x, hi.y);
        }
    }
}

// -------- gather1 fused: h = relu(agg + dis^2*xw1 + b1)  (warp per bin) --------
__global__ void gather1_kernel(const float* __restrict__ bsl1, const float* __restrict__ bkg1) {
    int warp = (blockIdx.x * blockDim.x + threadIdx.x) >> 5;
    if (warp >= NB) return;
    int lane = threadIdx.x & 31;
    int g = warp / N_NODES;
    int beg = g_off[warp], end = g_off[warp + 1];
    float disd = g_dis[warp];
    int gbase = g * N_NODES;
    float4 acc = make_float4(0.f, 0.f, 0.f, 0.f);
    int j = beg;
    for (; j + 1 < end; j += 2) {
        int s0 = g_csr[j], s1 = g_csr[j + 1];
        float n0 = disd * g_dis[gbase + s0];
        float n1 = disd * g_dis[gbase + s1];
        const float4 v0 = *(const float4*)&g_xw1[(gbase + s0) * H1 + (lane << 2)];
        const float4 v1 = *(const float4*)&g_xw1[(gbase + s1) * H1 + (lane << 2)];
        acc.x += n0 * v0.x + n1 * v1.x;
        acc.y += n0 * v0.y + n1 * v1.y;
        acc.z += n0 * v0.z + n1 * v1.z;
        acc.w += n0 * v0.w + n1 * v1.w;
    }
    if (j < end) {
        int s0 = g_csr[j];
        float n0 = disd * g_dis[gbase + s0];
        const float4 v0 = *(const float4*)&g_xw1[(gbase + s0) * H1 + (lane << 2)];
        acc.x += n0 * v0.x;
        acc.y += n0 * v0.y;
        acc.z += n0 * v0.z;
        acc.w += n0 * v0.w;
    }
    // self loop + bias + relu
    float ds2 = disd * disd;
    const float4 vs = *(const float4*)&g_xw1[warp * H1 + (lane << 2)];
    const float* b1 = (g == 0) ? bsl1 : (bkg1 + (g - 1) * H1);
    const float4 bv = *(const float4*)&b1[lane << 2];
    float4 h;
    h.x = fmaxf(acc.x + ds2 * vs.x + bv.x, 0.f);
    h.y = fmaxf(acc.y + ds2 * vs.y + bv.y, 0.f);
    h.z = fmaxf(acc.z + ds2 * vs.z + bv.z, 0.f);
    h.w = fmaxf(acc.w + ds2 * vs.w + bv.w, 0.f);
    *(float4*)&g_h[warp * H1 + (lane << 2)] = h;
}

// -------- gemm2: xw2 = h @ W2 --------
__global__ void gemm2_kernel(const float* __restrict__ Wsl2, const float* __restrict__ Wkg2) {
    __shared__ float hs[16 * 128];
    __shared__ float w2s[128 * 16];
    int g = blockIdx.y;
    int n0 = blockIdx.x * 16;
    const float* W2 = (g == 0) ? Wsl2 : (Wkg2 + (g - 1) * H1 * H2);
    int t = threadIdx.x;
    for (int idx = t; idx < H1 * H2; idx += 256) w2s[idx] = W2[idx];
    for (int idx = t; idx < 16 * H1; idx += 256) {
        int r = idx >> 7, k = idx & 127;
        int n = n0 + r;
        hs[idx] = (n < N_NODES) ? g_h[(g * N_NODES + n) * H1 + k] : 0.f;
    }
    __syncthreads();
    int r = t >> 4, j = t & 15;
    int n = n0 + r;
    if (n < N_NODES) {
        float acc = 0.f;
#pragma unroll 8
        for (int k = 0; k < H1; k++) acc += hs[r * 128 + k] * w2s[k * 16 + j];
        g_xw2[(g * N_NODES + n) * H2 + j] = acc;
    }
}

// -------- gather2 fused: emb = agg + dis^2*xw2 + b2  (thread per bin) --------
__global__ void gather2_kernel(const float* __restrict__ bsl2, const float* __restrict__ bkg2) {
    int bin = blockIdx.x * blockDim.x + threadIdx.x;
    if (bin >= NB) return;
    int g = bin / N_NODES;
    int beg = g_off[bin], end = g_off[bin + 1];
    float disd = g_dis[bin];
    int gbase = g * N_NODES;
    float4 a0 = make_float4(0.f, 0.f, 0.f, 0.f);
    float4 a1 = a0, a2 = a0, a3 = a0;
    for (int j = beg; j < end; j++) {
        int src = g_csr[j];
        float nrm = disd * g_dis[gbase + src];
        const float4* row = (const float4*)&g_xw2[(gbase + src) * H2];
        float4 v0 = row[0], v1 = row[1], v2 = row[2], v3 = row[3];
        a0.x += nrm * v0.x; a0.y += nrm * v0.y; a0.z += nrm * v0.z; a0.w += nrm * v0.w;
        a1.x += nrm * v1.x; a1.y += nrm * v1.y; a1.z += nrm * v1.z; a1.w += nrm * v1.w;
        a2.x += nrm * v2.x; a2.y += nrm * v2.y; a2.z += nrm * v2.z; a2.w += nrm * v2.w;
        a3.x += nrm * v3.x; a3.y += nrm * v3.y; a3.z += nrm * v3.z; a3.w += nrm * v3.w;
    }
    float ds2 = disd * disd;
    const float4* sr = (const float4*)&g_xw2[bin * H2];
    const float* b2 = (g == 0) ? bsl2 : (bkg2 + (g - 1) * H2);
    const float4* bb = (const float4*)b2;
    float4 s0 = sr[0], s1 = sr[1], s2 = sr[2], s3 = sr[3];
    float4 b0 = bb[0], b1 = bb[1], b2v = bb[2], b3 = bb[3];
    a0.x += ds2 * s0.x + b0.x; a0.y += ds2 * s0.y + b0.y;
    a0.z += ds2 * s0.z + b0.z; a0.w += ds2 * s0.w + b0.w;
    a1.x += ds2 * s1.x + b1.x; a1.y += ds2 * s1.y + b1.y;
    a1.z += ds2 * s1.z + b1.z; a1.w += ds2 * s1.w + b1.w;
    a2.x += ds2 * s2.x + b2v.x; a2.y += ds2 * s2.y + b2v.y;
    a2.z += ds2 * s2.z + b2v.z; a2.w += ds2 * s2.w + b2v.w;
    a3.x += ds2 * s3.x + b3.x; a3.y += ds2 * s3.y + b3.y;
    a3.z += ds2 * s3.z + b3.z; a3.w += ds2 * s3.w + b3.w;
    float4* o = (float4*)&g_emb[bin * H2];
    o[0] = a0; o[1] = a1; o[2] = a2; o[3] = a3;
}

// -------- per-edge CNN: 5 edge slots per 640-thread block, paired-pooled conv2 --------
struct CnnSmem {
    float w2s[32 * 9 * 64];   // 18432 floats
    float l1w[32 * 64];       // 2048
    float w1s[32 * 8];        // 256
    float c1b[32];
    float c2b[64];
    float l1b[32];
    float l2w[32];
    float l2b[4];             // pad: img 16B-aligned at 20900 floats
    float img[CNN_SUBS][2 * 14 * 16];       // 448 each
    float pp[CNN_SUBS][32 * 5 * 6 * 2];     // vertical pairs {p[y],p[y+1]}, 1920 each
    float feats[CNN_SUBS][64];
};

#define BARSYNC(id) asm volatile("bar.sync %0, 128;" :: "r"(id) : "memory")

__global__ __launch_bounds__(CNN_THREADS, 1)
void cnn_kernel(const int* __restrict__ sl_pos, const int* __restrict__ sl_neg,
                const float* __restrict__ conv1_w, const float* __restrict__ conv1_b,
                const float* __restrict__ conv2_w, const float* __restrict__ conv2_b,
                const float* __restrict__ lin1_w, const float* __restrict__ lin1_b,
                const float* __restrict__ lin2_w, const float* __restrict__ lin2_b,
                float* __restrict__ out) {
    extern __shared__ __align__(16) char smem_raw[];
    CnnSmem* s = reinterpret_cast<CnnSmem*>(smem_raw);
    int t = threadIdx.x;
    int sub = t >> 7;       // edge slot 0..4
    int wt = t & 127;       // thread within sub
    int barid = sub + 1;    // named barrier per sub

    // ---- load all weights once per block ----
    for (int i = t; i < 64 * 32 * 9; i += CNN_THREADS) {
        int o = i / 288;
        int rem = i - o * 288;  // c*9 + k
        s->w2s[rem * 64 + o] = conv2_w[i];
    }
    for (int i = t; i < 32 * 64; i += CNN_THREADS) s->l1w[i] = lin1_w[i];
    if (t < 256) s->w1s[t] = conv1_w[t];
    if (t < 32) s->c1b[t] = conv1_b[t];
    if (t < 64) s->c2b[t] = conv2_b[t];
    if (t >= 64 && t < 96) s->l1b[t - 64] = lin1_b[t - 64];
    if (t >= 96 && t < 128) s->l2w[t - 96] = lin2_w[t - 96];
    if (t == 128) s->l2b[0] = lin2_b[0];
    __syncthreads();

    // E_CNN % CNN_SUBS == 0 and base % CNN_SUBS == 0 => e = base+sub < E_CNN always
    for (int base = blockIdx.x * CNN_SUBS; base < E_CNN; base += gridDim.x * CNN_SUBS) {
        int e = base + sub;
        int n0, n1;
        if (e < SL_E) {
            n0 = sl_pos[e];
            n1 = sl_pos[SL_E + e];
        } else {
            n0 = sl_neg[e - SL_E];
            n1 = sl_neg[e];
        }

        // ---- phase 1: gather image [2][14][16] via float4 ----
        if (wt < 112) {
            int c = wt / 56;
            int rem = wt - c * 56;
            int k = rem >> 2;
            int q = (rem & 3) << 2;
            int node = c ? n1 : n0;
            float4 v = *(const float4*)&g_emb[(c_slot[k] * N_NODES + node) * H2 + q];
            *(float4*)&s->img[sub][c * 224 + k * 16 + q] = v;
        }
        BARSYNC(barid);

        // ---- phase 2: conv1 + maxpool -> vertical-pair array pp [c][yp][x][2] ----
        // only the 6x6 pooled region conv2 reads (x=6 column is dead)
        const float* img = s->img[sub];
        float* ppf = s->pp[sub];
        for (int idx = wt; idx < 32 * 6 * 6; idx += 128) {
            int o = idx / 36;
            int rem = idx - o * 36;
            int y = rem / 6;
            int xx = rem - y * 6;
            const float* wv = &s->w1s[o * 8];
            float w0 = wv[0], w1 = wv[1], w2 = wv[2], w3 = wv[3];
            float w4 = wv[4], w5 = wv[5], w6 = wv[6], w7 = wv[7];
            float bb = s->c1b[o];
            float m = -1e30f;
#pragma unroll
            for (int ii = 0; ii < 2; ii++) {
#pragma unroll
                for (int jj = 0; jj < 2; jj++) {
                    int i = 2 * y + ii, j = 2 * xx + jj;
                    const float* i0p = &img[i * 16 + j];
                    const float* i1p = &img[224 + i * 16 + j];
                    float v = bb + w0 * i0p[0] + w1 * i0p[1] + w2 * i0p[16] + w3 * i0p[17] +
                              w4 * i1p[0] + w5 * i1p[1] + w6 * i1p[16] + w7 * i1p[17];
                    m = fmaxf(m, v);
                }
            }
            // pair slots: lo of pair y (pp[.][y][x][0]), hi of pair y-1
            int pbase = (o * 5) * 6 + xx;
            if (y < 5) ppf[(pbase + y * 6) * 2] = m;
            if (y > 0) ppf[(pbase + (y - 1) * 6) * 2 + 1] = m;
        }
        BARSYNC(barid);

        // ---- phase 3: conv2 (f32x2 on prepacked vertical pairs) + pair-max shfl ----
        {
            int o = wt >> 1, half = wt & 1, i0 = half * 2;
            float bb = s->c2b[o];
            u64t acc2[4];
            u64t bb2 = pk2(bb, bb);
#pragma unroll
            for (int j = 0; j < 4; j++) acc2[j] = bb2;
            const u64t* pp = (const u64t*)s->pp[sub];   // [c][yp][x]
            for (int c = 0; c < 32; c++) {
                const u64t* pc = &pp[c * 30 + i0 * 6];
                const float* wp = &s->w2s[c * 9 * 64 + o];
#pragma unroll
                for (int di = 0; di < 3; di++) {
                    u64t pr0 = pc[di * 6 + 0], pr1 = pc[di * 6 + 1], pr2 = pc[di * 6 + 2];
                    u64t pr3 = pc[di * 6 + 3], pr4 = pc[di * 6 + 4], pr5 = pc[di * 6 + 5];
                    u64t prv[6] = {pr0, pr1, pr2, pr3, pr4, pr5};
#pragma unroll
                    for (int dj = 0; dj < 3; dj++) {
                        float w = wp[(di * 3 + dj) * 64];
                        u64t ww = pk2(w, w);
#pragma unroll
                        for (int j = 0; j < 4; j++)
                            acc2[j] = fma2(prv[dj + j], ww, acc2[j]);
                    }
                }
            }
            float m = -1e30f;
#pragma unroll
            for (int j = 0; j < 4; j++) {
                float2 f = upk2(acc2[j]);
                m = fmaxf(m, fmaxf(f.x, f.y));
            }
            float mo = fmaxf(m, __shfl_down_sync(0xffffffffu, m, 1));
            if ((wt & 1) == 0) s->feats[sub][o] = mo;
        }
        BARSYNC(barid);

        // ---- epilogue: warp 0 of sub (overlaps other warps' next gather) ----
        if (wt < 32) {
            float acc = s->l1b[wt];
            const float* fp = s->feats[sub];
#pragma unroll 16
            for (int d = 0; d < 64; d++) acc += fp[d] * s->l1w[wt * 64 + d];
            float h = fmaxf(acc, 0.f);
            float p = h * s->l2w[wt];
#pragma unroll
            for (int off = 16; off; off >>= 1) p += __shfl_down_sync(0xffffffffu, p, off);
            if (wt == 0) out[e] = 1.f / (1.f + expf(-(p + s->l2b[0])));
        }
        // no trailing barrier: feats[sub] is rewritten only after the NEXT
        // phase-3, which every warp reaches only after two more BARSYNCs.
    }
}

// -------- launch --------
extern "C" void kernel_launch(void* const* d_in, const int* in_sizes, int n_in,
                              void* d_out, int out_size) {
    const float* x       = (const float*)d_in[0];
    const int*   sl_pos  = (const int*)d_in[1];
    const int*   sl_neg  = (const int*)d_in[2];
    const int*   kg_edges= (const int*)d_in[3];
    const float* Wsl1    = (const float*)d_in[4];
    const float* bsl1    = (const float*)d_in[5];
    const float* Wsl2    = (const float*)d_in[6];
    const float* bsl2    = (const float*)d_in[7];
    const float* Wkg1    = (const float*)d_in[8];
    const float* bkg1    = (const float*)d_in[9];
    const float* Wkg2    = (const float*)d_in[10];
    const float* bkg2    = (const float*)d_in[11];
    const float* conv1_w = (const float*)d_in[12];
    const float* conv1_b = (const float*)d_in[13];
    const float* conv2_w = (const float*)d_in[14];
    const float* conv2_b = (const float*)d_in[15];
    const float* lin1_w  = (const float*)d_in[16];
    const float* lin1_b  = (const float*)d_in[17];
    const float* lin2_w  = (const float*)d_in[18];
    const float* lin2_b  = (const float*)d_in[19];
    float* out = (float*)d_out;

    void* p_deg;
    cudaGetSymbolAddress(&p_deg, g_deg);
    cudaMemsetAsync(p_deg, 0, sizeof(int) * NB);

    degree_kernel<<<(TOT_EDGES + 255) / 256, 256>>>(sl_pos, kg_edges);
    dis_kernel<<<(NB + 255) / 256, 256>>>();
    scan_local_kernel<<<SCAN_NBLK, SCAN_BS>>>();
    scan_top_kernel<<<1, 256>>>();
    scan_add_kernel<<<SCAN_NBLK, SCAN_BS>>>();
    fill_csr_kernel<<<(TOT_EDGES + 255) / 256, 256>>>(sl_pos, kg_edges);
    gemm1_kernel<<<dim3((N_NODES + 63) / 64, NG), 256>>>(x, Wsl1, Wkg1);
    gather1_kernel<<<(NB * 32 + 255) / 256, 256>>>(bsl1, bkg1);
    gemm2_kernel<<<dim3((N_NODES + 15) / 16, NG), 256>>>(Wsl2, Wkg2);
    gather2_kernel<<<(NB + 255) / 256, 256>>>(bsl2, bkg2);

    cudaFuncSetAttribute(cnn_kernel, cudaFuncAttributeMaxDynamicSharedMemorySize,
                         (int)sizeof(CnnSmem));
    cnn_kernel<<<148, CNN_THREADS, sizeof(CnnSmem)>>>(
        sl_pos, sl_neg, conv1_w, conv1_b, conv2_w, conv2_b,
        lin1_w, lin1_b, lin2_w, lin2_b, out);
}

// round 10
// speedup vs baseline: 1.4187x; 1.0010x over previous
#include <cuda_runtime.h>
#include <math.h>

#define N_NODES 20000
#define D_IN 256
#define H1 128
#define H2 16
#define KG_E 200000
#define SL_E 20000
#define NG 8
#define TOT_EDGES (SL_E + 7 * KG_E)
#define E_CNN 40000
#define CNN_SUBS 5
#define CNN_THREADS (128 * CNN_SUBS)   // 640
#define NB (NG * N_NODES)              // 160000 bins
#define SCAN_BS 1024
#define SCAN_NBLK ((NB + SCAN_BS - 1) / SCAN_BS)  // 157

// gemm1 tiling: 64 rows per tile, 313 tiles per graph, 2504 total
#define G1_PER_G 313
#define G1_TOT (G1_PER_G * NG)         // 2504
#define DEG_BLOCKS ((TOT_EDGES + 255) / 256)   // 5547
#define S1_TILES 256                   // gemm1 tiles carried by degree launch
#define S2_OFF   S1_TILES
#define S2_TILES 512                   // gemm1 tiles carried by fill launch
#define REST_OFF (S1_TILES + S2_TILES) // 768
#define REST_TILES (G1_TOT - REST_OFF) // 1736

// -------- packed f32x2 helpers (sm_100a) --------
typedef unsigned long long u64t;
__device__ __forceinline__ u64t pk2(float lo, float hi) {
    u64t r;
    asm("mov.b64 %0, {%1, %2};" : "=l"(r) : "r"(__float_as_uint(lo)), "r"(__float_as_uint(hi)));
    return r;
}
__device__ __forceinline__ u64t fma2(u64t a, u64t b, u64t c) {
    u64t d;
    asm("fma.rn.f32x2 %0, %1, %2, %3;" : "=l"(d) : "l"(a), "l"(b), "l"(c));
    return d;
}
__device__ __forceinline__ float2 upk2(u64t v) {
    unsigned int lo, hi;
    asm("mov.b64 {%0, %1}, %2;" : "=r"(lo), "=r"(hi) : "l"(v));
    return make_float2(__uint_as_float(lo), __uint_as_float(hi));
}

// -------- scratch (device globals; no allocation allowed) --------
__device__ float g_xw1[NG * N_NODES * H1];
__device__ float g_xw2[NG * N_NODES * H2];
__device__ float g_emb[NG * N_NODES * H2];
__device__ int   g_deg[NB];
__device__ float g_dis[NB];
__device__ int   g_off[NB + 1];
__device__ int   g_cur[NB];
__device__ int   g_csr[TOT_EDGES];
__device__ int   g_bsum[SCAN_NBLK];

// emb_all row k -> slot in g_emb (slot0=sl, 1..7 = ppi,reactome,corum,go_f,go_c,go_p,kegg)
__constant__ int c_slot[14] = {0, 2, 0, 7, 0, 4, 0, 3, 0, 5, 0, 6, 0, 1};

__device__ __forceinline__ void decode_edge(int eid, const int* __restrict__ sl_pos,
                                            const int* __restrict__ kg_edges,
                                            int& g, int& src, int& dst) {
    if (eid < SL_E) {
        g = 0;
        src = sl_pos[eid];
        dst = sl_pos[SL_E + eid];
    } else {
        int r = eid - SL_E;
        int gg = r / KG_E;
        int i = r - gg * KG_E;
        g = gg + 1;
        const int* base = kg_edges + gg * 2 * KG_E;
        src = base[i];
        dst = base[KG_E + i];
    }
}

// -------- gemm1 tile body (64 rows x 128 cols of one graph) --------
__device__ void gemm1_tile(const float* __restrict__ x,
                           const float* __restrict__ Wsl1,
                           const float* __restrict__ Wkg1, int tile) {
    __shared__ float As2[16][64];   // [k][row]
    __shared__ float Bs[16][128];
    int g = tile / G1_PER_G;
    int row0 = (tile - g * G1_PER_G) * 64;
    const float* B = (g == 0) ? Wsl1 : (Wkg1 + (g - 1) * D_IN * H1);
    int t = threadIdx.x;
    int tx = t & 31, ty = t >> 5;
    int ty8 = ty << 3;
    u64t acc2[8][2];
#pragma unroll
    for (int r = 0; r < 8; r++) {
        acc2[r][0] = 0ull;
        acc2[r][1] = 0ull;
    }
    int ai = t >> 2, aq = (t & 3) << 2;
    for (int kb = 0; kb < D_IN; kb += 16) {
        int arow = row0 + ai;
        float4 av = make_float4(0.f, 0.f, 0.f, 0.f);
        if (arow < N_NODES) av = *(const float4*)&x[arow * D_IN + kb + aq];
        As2[aq + 0][ai] = av.x;
        As2[aq + 1][ai] = av.y;
        As2[aq + 2][ai] = av.z;
        As2[aq + 3][ai] = av.w;
#pragma unroll
        for (int l = 0; l < 2; l++) {
            int lin = t + l * 256;
            int bk = lin >> 5, bq = (lin & 31) << 2;
            *(float4*)&Bs[bk][bq] = *(const float4*)&B[(kb + bk) * H1 + bq];
        }
        __syncthreads();
#pragma unroll
        for (int k = 0; k < 16; k++) {
            float4 alo = *(float4*)&As2[k][ty8];
            float4 ahi = *(float4*)&As2[k][ty8 + 4];
            float4 b = *(float4*)&Bs[k][tx << 2];
            u64t b01 = pk2(b.x, b.y);
            u64t b23 = pk2(b.z, b.w);
            float ar[8] = {alo.x, alo.y, alo.z, alo.w, ahi.x, ahi.y, ahi.z, ahi.w};
#pragma unroll
            for (int r = 0; r < 8; r++) {
                u64t aa = pk2(ar[r], ar[r]);
                acc2[r][0] = fma2(aa, b01, acc2[r][0]);
                acc2[r][1] = fma2(aa, b23, acc2[r][1]);
            }
        }
        __syncthreads();
    }
#pragma unroll
    for (int r = 0; r < 8; r++) {
        int row = row0 + ty8 + r;
        if (row < N_NODES) {
            float2 lo = upk2(acc2[r][0]);
            float2 hi = upk2(acc2[r][1]);
            *(float4*)&g_xw1[(g * N_NODES + row) * H1 + (tx << 2)] =
                make_float4(lo.x, lo.y, hi.x, hi.y);
        }
    }
}

// -------- K1: degree histogram blocks + gemm1 slice 1 --------
__global__ __launch_bounds__(256)
void deg_gemm1_kernel(const float* __restrict__ x,
                      const float* __restrict__ Wsl1, const float* __restrict__ Wkg1,
                      const int* __restrict__ sl_pos, const int* __restrict__ kg_edges) {
    if (blockIdx.x < DEG_BLOCKS) {
        int e = blockIdx.x * 256 + threadIdx.x;
        if (e >= TOT_EDGES) return;
        int g, dst;
        if (e < SL_E) {
            g = 0;
            dst = sl_pos[SL_E + e];
        } else {
            int r = e - SL_E;
            int gg = r / KG_E;
            int i = r - gg * KG_E;
            g = gg + 1;
            dst = kg_edges[gg * 2 * KG_E + KG_E + i];
        }
        atomicAdd(&g_deg[g * N_NODES + dst], 1);
    } else {
        gemm1_tile(x, Wsl1, Wkg1, blockIdx.x - DEG_BLOCKS);
    }
}

// -------- exclusive scan of g_deg -> g_off (also emits g_dis) --------
__global__ void scan_local_kernel() {
    __shared__ int wsum[32];
    int i = blockIdx.x * SCAN_BS + threadIdx.x;
    int lane = threadIdx.x & 31, wid = threadIdx.x >> 5;
    int v = (i < NB) ? g_deg[i] : 0;
    if (i < NB) g_dis[i] = rsqrtf((float)(v + 1));
    int x = v;
#pragma unroll
    for (int d = 1; d < 32; d <<= 1) {
        int y = __shfl_up_sync(0xffffffffu, x, d);
        if (lane >= d) x += y;
    }
    if (lane == 31) wsum[wid] = x;
    __syncthreads();
    if (wid == 0) {
        int s = wsum[lane];
        int t2 = s;
#pragma unroll
        for (int d = 1; d < 32; d <<= 1) {
            int y = __shfl_up_sync(0xffffffffu, t2, d);
            if (lane >= d) t2 += y;
        }
        wsum[lane] = t2 - s;
        if (lane == 31) g_bsum[blockIdx.x] = t2;
    }
    __syncthreads();
    if (i < NB) g_off[i] = x - v + wsum[wid];
}

__global__ void scan_top_kernel() {
    __shared__ int wsum[8];
    int lane = threadIdx.x & 31, wid = threadIdx.x >> 5;
    int v = (threadIdx.x < SCAN_NBLK) ? g_bsum[threadIdx.x] : 0;
    int x = v;
#pragma unroll
    for (int d = 1; d < 32; d <<= 1) {
        int y = __shfl_up_sync(0xffffffffu, x, d);
        if (lane >= d) x += y;
    }
    if (lane == 31) wsum[wid] = x;
    __syncthreads();
    if (wid == 0) {
        int s = (lane < 8) ? wsum[lane] : 0;
        int t2 = s;
#pragma unroll
        for (int d = 1; d < 32; d <<= 1) {
            int y = __shfl_up_sync(0xffffffffu, t2, d);
            if (lane >= d) t2 += y;
        }
        if (lane < 8) wsum[lane] = t2 - s;
    }
    __syncthreads();
    if (threadIdx.x < SCAN_NBLK) g_bsum[threadIdx.x] = x - v + wsum[wid];
}

__global__ void scan_add_kernel() {
    int i = blockIdx.x * SCAN_BS + threadIdx.x;
    if (i < NB) {
        int o = g_off[i] + g_bsum[blockIdx.x];
        g_off[i] = o;
        g_cur[i] = o;
        if (i == NB - 1) g_off[NB] = o + g_deg[i];
    }
}

// -------- K5: CSR fill blocks + gemm1 slice 2 --------
__global__ __launch_bounds__(256)
void fill_gemm1_kernel(const float* __restrict__ x,
                       const float* __restrict__ Wsl1, const float* __restrict__ Wkg1,
                       const int* __restrict__ sl_pos, const int* __restrict__ kg_edges) {
    if (blockIdx.x < DEG_BLOCKS) {
        int e = blockIdx.x * 256 + threadIdx.x;
        if (e >= TOT_EDGES) return;
        int g, src, dst;
        decode_edge(e, sl_pos, kg_edges, g, src, dst);
        int pos = atomicAdd(&g_cur[g * N_NODES + dst], 1);
        g_csr[pos] = src;
    } else {
        gemm1_tile(x, Wsl1, Wkg1, S2_OFF + blockIdx.x - DEG_BLOCKS);
    }
}

// -------- K6: remaining gemm1 tiles --------
__global__ __launch_bounds__(256)
void gemm1_rest_kernel(const float* __restrict__ x,
                       const float* __restrict__ Wsl1, const float* __restrict__ Wkg1) {
    gemm1_tile(x, Wsl1, Wkg1, REST_OFF + blockIdx.x);
}

// -------- fused gather1+gemm2: warp gathers h[128], block computes h@W2 --------
__global__ __launch_bounds__(256)
void gcn2_kernel(const float* __restrict__ Wsl2, const float* __restrict__ Wkg2,
                 const float* __restrict__ bsl1, const float* __restrict__ bkg1) {
    __shared__ float hsm[8][132];   // padded: rows differ by 4 banks
    __shared__ float w2s[H1 * H2];
    int g = blockIdx.y;
    const float* W2 = (g == 0) ? Wsl2 : (Wkg2 + (g - 1) * H1 * H2);
    const float* b1 = (g == 0) ? bsl1 : (bkg1 + (g - 1) * H1);
    int t = threadIdx.x;
    int wid = t >> 5, lane = t & 31;
    for (int i = t; i < 512; i += 256)
        ((float4*)w2s)[i] = ((const float4*)W2)[i];

    int node = blockIdx.x * 8 + wid;          // 2500*8 == N_NODES exactly
    int bin = g * N_NODES + node;
    int beg = g_off[bin], end = g_off[bin + 1];
    float disd = g_dis[bin];
    int gbase = g * N_NODES;
    float4 acc = make_float4(0.f, 0.f, 0.f, 0.f);
    int j = beg;
    for (; j + 1 < end; j += 2) {
        int s0 = g_csr[j], s1 = g_csr[j + 1];
        float n0 = disd * g_dis[gbase + s0];
        float n1 = disd * g_dis[gbase + s1];
        const float4 v0 = *(const float4*)&g_xw1[(gbase + s0) * H1 + (lane << 2)];
        const float4 v1 = *(const float4*)&g_xw1[(gbase + s1) * H1 + (lane << 2)];
        acc.x += n0 * v0.x + n1 * v1.x;
        acc.y += n0 * v0.y + n1 * v1.y;
        acc.z += n0 * v0.z + n1 * v1.z;
        acc.w += n0 * v0.w + n1 * v1.w;
    }
    if (j < end) {
        int s0 = g_csr[j];
        float n0 = disd * g_dis[gbase + s0];
        const float4 v0 = *(const float4*)&g_xw1[(gbase + s0) * H1 + (lane << 2)];
        acc.x += n0 * v0.x;
        acc.y += n0 * v0.y;
        acc.z += n0 * v0.z;
        acc.w += n0 * v0.w;
    }
    float ds2 = disd * disd;
    const float4 vs = *(const float4*)&g_xw1[bin * H1 + (lane << 2)];
    const float4 bv = *(const float4*)&b1[lane << 2];
    float4 h;
    h.x = fmaxf(acc.x + ds2 * vs.x + bv.x, 0.f);
    h.y = fmaxf(acc.y + ds2 * vs.y + bv.y, 0.f);
    h.z = fmaxf(acc.z + ds2 * vs.z + bv.z, 0.f);
    h.w = fmaxf(acc.w + ds2 * vs.w + bv.w, 0.f);
    *(float4*)&hsm[wid][lane << 2] = h;
    __syncthreads();

    // gemm2: 128 threads, thread -> (node n, output j); same k-order as before
    if (t < 128) {
        int n = t >> 4, jj = t & 15;
        float a = 0.f;
#pragma unroll 8
        for (int k = 0; k < H1; k++) a += hsm[n][k] * w2s[k * 16 + jj];
        g_xw2[(g * N_NODES + blockIdx.x * 8 + n) * H2 + jj] = a;
    }
}

// -------- gather2 fused: emb = agg + dis^2*xw2 + b2  (thread per bin) --------
__global__ void gather2_kernel(const float* __restrict__ bsl2, const float* __restrict__ bkg2) {
    int bin = blockIdx.x * blockDim.x + threadIdx.x;
    if (bin >= NB) return;
    int g = bin / N_NODES;
    int beg = g_off[bin], end = g_off[bin + 1];
    float disd = g_dis[bin];
    int gbase = g * N_NODES;
    float4 a0 = make_float4(0.f, 0.f, 0.f, 0.f);
    float4 a1 = a0, a2 = a0, a3 = a0;
    for (int j = beg; j < end; j++) {
        int src = g_csr[j];
        float nrm = disd * g_dis[gbase + src];
        const float4* row = (const float4*)&g_xw2[(gbase + src) * H2];
        float4 v0 = row[0], v1 = row[1], v2 = row[2], v3 = row[3];
        a0.x += nrm * v0.x; a0.y += nrm * v0.y; a0.z += nrm * v0.z; a0.w += nrm * v0.w;
        a1.x += nrm * v1.x; a1.y += nrm * v1.y; a1.z += nrm * v1.z; a1.w += nrm * v1.w;
        a2.x += nrm * v2.x; a2.y += nrm * v2.y; a2.z += nrm * v2.z; a2.w += nrm * v2.w;
        a3.x += nrm * v3.x; a3.y += nrm * v3.y; a3.z += nrm * v3.z; a3.w += nrm * v3.w;
    }
    float ds2 = disd * disd;
    const float4* sr = (const float4*)&g_xw2[bin * H2];
    const float* b2 = (g == 0) ? bsl2 : (bkg2 + (g - 1) * H2);
    const float4* bb = (const float4*)b2;
    float4 s0 = sr[0], s1 = sr[1], s2 = sr[2], s3 = sr[3];
    float4 b0 = bb[0], b1 = bb[1], b2v = bb[2], b3 = bb[3];
    a0.x += ds2 * s0.x + b0.x; a0.y += ds2 * s0.y + b0.y;
    a0.z += ds2 * s0.z + b0.z; a0.w += ds2 * s0.w + b0.w;
    a1.x += ds2 * s1.x + b1.x; a1.y += ds2 * s1.y + b1.y;
    a1.z += ds2 * s1.z + b1.z; a1.w += ds2 * s1.w + b1.w;
    a2.x += ds2 * s2.x + b2v.x; a2.y += ds2 * s2.y + b2v.y;
    a2.z += ds2 * s2.z + b2v.z; a2.w += ds2 * s2.w + b2v.w;
    a3.x += ds2 * s3.x + b3.x; a3.y += ds2 * s3.y + b3.y;
    a3.z += ds2 * s3.z + b3.z; a3.w += ds2 * s3.w + b3.w;
    float4* o = (float4*)&g_emb[bin * H2];
    o[0] = a0; o[1] = a1; o[2] = a2; o[3] = a3;
}

// -------- per-edge CNN: 5 edge slots per 640-thread block, paired-pooled conv2 --------
struct CnnSmem {
    float w2s[32 * 9 * 64];   // 18432 floats
    float l1w[32 * 64];       // 2048
    float w1s[32 * 8];        // 256
    float c1b[32];
    float c2b[64];
    float l1b[32];
    float l2w[32];
    float l2b[4];             // pad: img 16B-aligned at 20900 floats
    float img[CNN_SUBS][2 * 14 * 16];       // 448 each
    float pp[CNN_SUBS][32 * 5 * 6 * 2];     // vertical pairs {p[y],p[y+1]}, 1920 each
    float feats[CNN_SUBS][64];
};

#define BARSYNC(id) asm volatile("bar.sync %0, 128;" :: "r"(id) : "memory")

__global__ __launch_bounds__(CNN_THREADS, 1)
void cnn_kernel(const int* __restrict__ sl_pos, const int* __restrict__ sl_neg,
                const float* __restrict__ conv1_w, const float* __restrict__ conv1_b,
                const float* __restrict__ conv2_w, const float* __restrict__ conv2_b,
                const float* __restrict__ lin1_w, const float* __restrict__ lin1_b,
                const float* __restrict__ lin2_w, const float* __restrict__ lin2_b,
                float* __restrict__ out) {
    extern __shared__ __align__(16) char smem_raw[];
    CnnSmem* s = reinterpret_cast<CnnSmem*>(smem_raw);
    int t = threadIdx.x;
    int sub = t >> 7;       // edge slot 0..4
    int wt = t & 127;       // thread within sub
    int barid = sub + 1;    // named barrier per sub

    // ---- load all weights once per block ----
    for (int i = t; i < 64 * 32 * 9; i += CNN_THREADS) {
        int o = i / 288;
        int rem = i - o * 288;  // c*9 + k
        s->w2s[rem * 64 + o] = conv2_w[i];
    }
    for (int i = t; i < 32 * 64; i += CNN_THREADS) s->l1w[i] = lin1_w[i];
    if (t < 256) s->w1s[t] = conv1_w[t];
    if (t < 32) s->c1b[t] = conv1_b[t];
    if (t < 64) s->c2b[t] = conv2_b[t];
    if (t >= 64 && t < 96) s->l1b[t - 64] = lin1_b[t - 64];
    if (t >= 96 && t < 128) s->l2w[t - 96] = lin2_w[t - 96];
    if (t == 128) s->l2b[0] = lin2_b[0];
    __syncthreads();

    // E_CNN % CNN_SUBS == 0 and base % CNN_SUBS == 0 => e = base+sub < E_CNN always
    for (int base = blockIdx.x * CNN_SUBS; base < E_CNN; base += gridDim.x * CNN_SUBS) {
        int e = base + sub;
        int n0, n1;
        if (e < SL_E) {
            n0 = sl_pos[e];
            n1 = sl_pos[SL_E + e];
        } else {
            n0 = sl_neg[e - SL_E];
            n1 = sl_neg[e];
        }

        // ---- phase 1: gather image [2][14][16] via float4 ----
        if (wt < 112) {
            int c = wt / 56;
            int rem = wt - c * 56;
            int k = rem >> 2;
            int q = (rem & 3) << 2;
            int node = c ? n1 : n0;
            float4 v = *(const float4*)&g_emb[(c_slot[k] * N_NODES + node) * H2 + q];
            *(float4*)&s->img[sub][c * 224 + k * 16 + q] = v;
        }
        BARSYNC(barid);

        // ---- phase 2: conv1 + maxpool -> vertical-pair array pp [c][yp][x][2] ----
        const float* img = s->img[sub];
        float* ppf = s->pp[sub];
        for (int idx = wt; idx < 32 * 6 * 6; idx += 128) {
            int o = idx / 36;
            int rem = idx - o * 36;
            int y = rem / 6;
            int xx = rem - y * 6;
            const float* wv = &s->w1s[o * 8];
            float w0 = wv[0], w1 = wv[1], w2 = wv[2], w3 = wv[3];
            float w4 = wv[4], w5 = wv[5], w6 = wv[6], w7 = wv[7];
            float bb = s->c1b[o];
            float m = -1e30f;
#pragma unroll
            for (int ii = 0; ii < 2; ii++) {
#pragma unroll
                for (int jj = 0; jj < 2; jj++) {
                    int i = 2 * y + ii, j = 2 * xx + jj;
                    const float* i0p = &img[i * 16 + j];
                    const float* i1p = &img[224 + i * 16 + j];
                    float v = bb + w0 * i0p[0] + w1 * i0p[1] + w2 * i0p[16] + w3 * i0p[17] +
                              w4 * i1p[0] + w5 * i1p[1] + w6 * i1p[16] + w7 * i1p[17];
                    m = fmaxf(m, v);
                }
            }
            int pbase = (o * 5) * 6 + xx;
            if (y < 5) ppf[(pbase + y * 6) * 2] = m;
            if (y > 0) ppf[(pbase + (y - 1) * 6) * 2 + 1] = m;
        }
        BARSYNC(barid);

        // ---- phase 3: conv2 (f32x2 on prepacked vertical pairs) + pair-max shfl ----
        {
            int o = wt >> 1, half = wt & 1, i0 = half * 2;
            float bb = s->c2b[o];
            u64t acc2[4];
            u64t bb2 = pk2(bb, bb);
#pragma unroll
            for (int j = 0; j < 4; j++) acc2[j] = bb2;
            const u64t* pp = (const u64t*)s->pp[sub];   // [c][yp][x]
            for (int c = 0; c < 32; c++) {
                const u64t* pc = &pp[c * 30 + i0 * 6];
                const float* wp = &s->w2s[c * 9 * 64 + o];
#pragma unroll
                for (int di = 0; di < 3; di++) {
                    u64t pr0 = pc[di * 6 + 0], pr1 = pc[di * 6 + 1], pr2 = pc[di * 6 + 2];
                    u64t pr3 = pc[di * 6 + 3], pr4 = pc[di * 6 + 4], pr5 = pc[di * 6 + 5];
                    u64t prv[6] = {pr0, pr1, pr2, pr3, pr4, pr5};
#pragma unroll
                    for (int dj = 0; dj < 3; dj++) {
                        float w = wp[(di * 3 + dj) * 64];
                        u64t ww = pk2(w, w);
#pragma unroll
                        for (int j = 0; j < 4; j++)
                            acc2[j] = fma2(prv[dj + j], ww, acc2[j]);
                    }
                }
            }
            float m = -1e30f;
#pragma unroll
            for (int j = 0; j < 4; j++) {
                float2 f = upk2(acc2[j]);
                m = fmaxf(m, fmaxf(f.x, f.y));
            }
            float mo = fmaxf(m, __shfl_down_sync(0xffffffffu, m, 1));
            if ((wt & 1) == 0) s->feats[sub][o] = mo;
        }
        BARSYNC(barid);

        // ---- epilogue: warp 0 of sub (overlaps other warps' next gather) ----
        if (wt < 32) {
            float acc = s->l1b[wt];
            const float* fp = s->feats[sub];
#pragma unroll 16
            for (int d = 0; d < 64; d++) acc += fp[d] * s->l1w[wt * 64 + d];
            float h = fmaxf(acc, 0.f);
            float p = h * s->l2w[wt];
#pragma unroll
            for (int off = 16; off; off >>= 1) p += __shfl_down_sync(0xffffffffu, p, off);
            if (wt == 0) out[e] = 1.f / (1.f + expf(-(p + s->l2b[0])));
        }
        // no trailing barrier: feats[sub] is rewritten only after the NEXT
        // phase-3, which every warp reaches only after two more BARSYNCs.
    }
}

// -------- launch (single stream; preproc co-scheduled with gemm1 slices) --------
extern "C" void kernel_launch(void* const* d_in, const int* in_sizes, int n_in,
                              void* d_out, int out_size) {
    const float* x       = (const float*)d_in[0];
    const int*   sl_pos  = (const int*)d_in[1];
    const int*   sl_neg  = (const int*)d_in[2];
    const int*   kg_edges= (const int*)d_in[3];
    const float* Wsl1    = (const float*)d_in[4];
    const float* bsl1    = (const float*)d_in[5];
    const float* Wsl2    = (const float*)d_in[6];
    const float* bsl2    = (const float*)d_in[7];
    const float* Wkg1    = (const float*)d_in[8];
    const float* bkg1    = (const float*)d_in[9];
    const float* Wkg2    = (const float*)d_in[10];
    const float* bkg2    = (const float*)d_in[11];
    const float* conv1_w = (const float*)d_in[12];
    const float* conv1_b = (const float*)d_in[13];
    const float* conv2_w = (const float*)d_in[14];
    const float* conv2_b = (const float*)d_in[15];
    const float* lin1_w  = (const float*)d_in[16];
    const float* lin1_b  = (const float*)d_in[17];
    const float* lin2_w  = (const float*)d_in[18];
    const float* lin2_b  = (const float*)d_in[19];
    float* out = (float*)d_out;

    void* p_deg;
    cudaGetSymbolAddress(&p_deg, g_deg);
    cudaMemsetAsync(p_deg, 0, sizeof(int) * NB);

    deg_gemm1_kernel<<<DEG_BLOCKS + S1_TILES, 256>>>(x, Wsl1, Wkg1, sl_pos, kg_edges);
    scan_local_kernel<<<SCAN_NBLK, SCAN_BS>>>();
    scan_top_kernel<<<1, 256>>>();
    scan_add_kernel<<<SCAN_NBLK, SCAN_BS>>>();
    fill_gemm1_kernel<<<DEG_BLOCKS + S2_TILES, 256>>>(x, Wsl1, Wkg1, sl_pos, kg_edges);
    gemm1_rest_kernel<<<REST_TILES, 256>>>(x, Wsl1, Wkg1);
    gcn2_kernel<<<dim3(2500, NG), 256>>>(Wsl2, Wkg2, bsl1, bkg1);
    gather2_kernel<<<(NB + 255) / 256, 256>>>(bsl2, bkg2);

    cudaFuncSetAttribute(cnn_kernel, cudaFuncAttributeMaxDynamicSharedMemorySize,
                         (int)sizeof(CnnSmem));
    cnn_kernel<<<148, CNN_THREADS, sizeof(CnnSmem)>>>(
        sl_pos, sl_neg, conv1_w, conv1_b, conv2_w, conv2_b,
        lin1_w, lin1_b, lin2_w, lin2_b, out);
}